// round 4
// baseline (speedup 1.0000x reference)
#include <cuda_runtime.h>
#include <math.h>

// Problem constants
#define Hdim   1024
#define NHEAD  16
#define HD     64
#define Bv     2
#define Sv     2048
#define Mrows  (Bv * Sv)   // 4096
#define EPSLN  1e-5f

// ---------------------------------------------------------------------------
// Device scratch (no cudaMalloc allowed)
// ---------------------------------------------------------------------------
__device__ float g_xn[Mrows * Hdim];
__device__ float g_q [Mrows * Hdim];
__device__ float g_k [Mrows * Hdim];
__device__ float g_v [Mrows * Hdim];
__device__ float g_ao[Mrows * Hdim];

// ---------------------------------------------------------------------------
// LayerNorm: one block per row (1024 cols), 256 threads, float4 per thread
// ---------------------------------------------------------------------------
__global__ __launch_bounds__(256) void ln_kernel(
    const float* __restrict__ x, const float* __restrict__ gamma,
    const float* __restrict__ beta, float* __restrict__ xn)
{
    int row = blockIdx.x;
    int t = threadIdx.x;
    const float* xr = x + (size_t)row * Hdim;
    float4 f = *(const float4*)(xr + t * 4);
    float s  = f.x + f.y + f.z + f.w;
    float s2 = f.x*f.x + f.y*f.y + f.z*f.z + f.w*f.w;

    __shared__ float red[20];
    #pragma unroll
    for (int o = 16; o > 0; o >>= 1) {
        s  += __shfl_down_sync(0xffffffffu, s,  o);
        s2 += __shfl_down_sync(0xffffffffu, s2, o);
    }
    int lane = t & 31, w = t >> 5;
    if (lane == 0) { red[w] = s; red[8 + w] = s2; }
    __syncthreads();
    if (t == 0) {
        float a = 0.f, b = 0.f;
        #pragma unroll
        for (int i = 0; i < 8; i++) { a += red[i]; b += red[8 + i]; }
        float mu  = a * (1.0f / Hdim);
        float var = b * (1.0f / Hdim) - mu * mu;
        red[16] = mu;
        red[17] = rsqrtf(var + EPSLN);
    }
    __syncthreads();
    float mu = red[16], rs = red[17];
    float4 g  = *(const float4*)(gamma + t * 4);
    float4 be = *(const float4*)(beta  + t * 4);
    float4 o;
    o.x = (f.x - mu) * rs * g.x + be.x;
    o.y = (f.y - mu) * rs * g.y + be.y;
    o.z = (f.z - mu) * rs * g.z + be.z;
    o.w = (f.w - mu) * rs * g.w + be.w;
    *(float4*)(xn + (size_t)row * Hdim + t * 4) = o;
}

// ---------------------------------------------------------------------------
// GEMM (NT): C[m][n] = sum_k A[m][k] * W[n][k]  (+ bias[n] + resid[m][n])
// BM=128, BN=64, BK=16, 256 threads, 8x4 micro-tile per thread
// ---------------------------------------------------------------------------
#define BM 128
#define BN 64
#define BK 16

__global__ __launch_bounds__(256) void gemm_nt_kernel(
    const float* __restrict__ A, const float* __restrict__ W,
    float* __restrict__ C, const float* __restrict__ bias,
    const float* __restrict__ resid, int M, int N, int K)
{
    __shared__ float As[BK][BM];
    __shared__ float Bs[BK][BN];

    int t  = threadIdx.x;
    int n0 = blockIdx.x * BN;
    int m0 = blockIdx.y * BM;
    int tx = t & 15;       // n direction, 4 cols each
    int ty = t >> 4;       // m direction, 8 rows each
    int ar = t >> 2;       // 0..63
    int ak = (t & 3) << 2; // 0,4,8,12

    float acc[8][4];
    #pragma unroll
    for (int i = 0; i < 8; i++)
        #pragma unroll
        for (int j = 0; j < 4; j++) acc[i][j] = 0.f;

    const float* Ap = A + (size_t)(m0 + ar) * K + ak;
    const float* Wp = W + (size_t)(n0 + ar) * K + ak;

    for (int kt = 0; kt < K; kt += BK) {
        float4 fa0 = *(const float4*)(Ap + kt);
        float4 fa1 = *(const float4*)(Ap + kt + (size_t)64 * K);
        float4 fb  = *(const float4*)(Wp + kt);
        As[ak + 0][ar]      = fa0.x;  As[ak + 1][ar]      = fa0.y;
        As[ak + 2][ar]      = fa0.z;  As[ak + 3][ar]      = fa0.w;
        As[ak + 0][ar + 64] = fa1.x;  As[ak + 1][ar + 64] = fa1.y;
        As[ak + 2][ar + 64] = fa1.z;  As[ak + 3][ar + 64] = fa1.w;
        Bs[ak + 0][ar] = fb.x;  Bs[ak + 1][ar] = fb.y;
        Bs[ak + 2][ar] = fb.z;  Bs[ak + 3][ar] = fb.w;
        __syncthreads();

        #pragma unroll
        for (int kk = 0; kk < BK; kk++) {
            float4 a0 = *(const float4*)&As[kk][ty * 8];
            float4 a1 = *(const float4*)&As[kk][ty * 8 + 4];
            float4 b  = *(const float4*)&Bs[kk][tx * 4];
            float av[8] = {a0.x, a0.y, a0.z, a0.w, a1.x, a1.y, a1.z, a1.w};
            float bv[4] = {b.x, b.y, b.z, b.w};
            #pragma unroll
            for (int ii = 0; ii < 8; ii++)
                #pragma unroll
                for (int jj = 0; jj < 4; jj++)
                    acc[ii][jj] += av[ii] * bv[jj];
        }
        __syncthreads();
    }

    int n = n0 + tx * 4;
    float4 bb = make_float4(0.f, 0.f, 0.f, 0.f);
    if (bias) bb = *(const float4*)(bias + n);
    #pragma unroll
    for (int ii = 0; ii < 8; ii++) {
        int m = m0 + ty * 8 + ii;
        float4 o = make_float4(acc[ii][0] + bb.x, acc[ii][1] + bb.y,
                               acc[ii][2] + bb.z, acc[ii][3] + bb.w);
        if (resid) {
            float4 r = *(const float4*)(resid + (size_t)m * N + n);
            o.x += r.x; o.y += r.y; o.z += r.z; o.w += r.w;
        }
        *(float4*)(C + (size_t)m * N + n) = o;
    }
}

// ---------------------------------------------------------------------------
// Flash-style attention: one CTA per (64-query tile, head, batch).
// Q,K in smem d-major (transposed); V row-major; S stored [key][query].
// Online softmax with per-row running (m, l).
// ---------------------------------------------------------------------------
#define AT   64
#define SSTR 68   // smem stride: 16B-aligned rows, low-conflict columns
#define ATTN_SMEM (4 * 64 * SSTR * 4 + 3 * 64 * 4)  // 70400 B

__global__ __launch_bounds__(256) void attn_kernel(
    const float* __restrict__ q, const float* __restrict__ k,
    const float* __restrict__ v, float* __restrict__ o)
{
    extern __shared__ float sm[];
    float* Qs    = sm;                // [d][i], 64 x SSTR
    float* Ks    = Qs + 64 * SSTR;    // [d][j]
    float* Vs    = Ks + 64 * SSTR;    // [j][c]
    float* Ss    = Vs + 64 * SSTR;    // [j][i]
    float* row_m = Ss + 64 * SSTR;    // [64]
    float* row_l = row_m + 64;        // [64]
    float* row_a = row_l + 64;        // [64]

    int t  = threadIdx.x;
    int m0 = blockIdx.x * AT;
    int h  = blockIdx.y;
    int b  = blockIdx.z;
    size_t base = (size_t)b * Sv * Hdim + (size_t)h * HD;

    int r  = t >> 2;          // 0..63
    int d4 = (t & 3) << 4;    // 0,16,32,48

    // Load Q tile, pre-scaled by 1/sqrt(HD), transposed to [d][i]
    {
        const float* qp = q + base + (size_t)(m0 + r) * Hdim + d4;
        const float sc = 0.125f;  // 1/sqrt(64)
        #pragma unroll
        for (int u = 0; u < 16; u += 4) {
            float4 f = *(const float4*)(qp + u);
            Qs[(d4 + u + 0) * SSTR + r] = f.x * sc;
            Qs[(d4 + u + 1) * SSTR + r] = f.y * sc;
            Qs[(d4 + u + 2) * SSTR + r] = f.z * sc;
            Qs[(d4 + u + 3) * SSTR + r] = f.w * sc;
        }
    }
    if (t < 64) { row_m[t] = -1e30f; row_l[t] = 0.f; }

    int tx = t & 15, ty = t >> 4;
    int i0 = ty * 4, j0 = tx * 4;
    float oacc[4][4];
    #pragma unroll
    for (int ii = 0; ii < 4; ii++)
        #pragma unroll
        for (int jj = 0; jj < 4; jj++) oacc[ii][jj] = 0.f;

    for (int kv0 = 0; kv0 < Sv; kv0 += AT) {
        // Load K transposed [d][j], V straight [j][c]
        const float* kp = k + base + (size_t)(kv0 + r) * Hdim + d4;
        const float* vp = v + base + (size_t)(kv0 + r) * Hdim + d4;
        #pragma unroll
        for (int u = 0; u < 16; u += 4) {
            float4 f = *(const float4*)(kp + u);
            Ks[(d4 + u + 0) * SSTR + r] = f.x;
            Ks[(d4 + u + 1) * SSTR + r] = f.y;
            Ks[(d4 + u + 2) * SSTR + r] = f.z;
            Ks[(d4 + u + 3) * SSTR + r] = f.w;
        }
        #pragma unroll
        for (int u = 0; u < 16; u += 4)
            *(float4*)&Vs[r * SSTR + d4 + u] = *(const float4*)(vp + u);
        __syncthreads();

        // S = Q K^T  (already scaled via Q)
        float sacc[4][4];
        #pragma unroll
        for (int ii = 0; ii < 4; ii++)
            #pragma unroll
            for (int jj = 0; jj < 4; jj++) sacc[ii][jj] = 0.f;
        #pragma unroll 8
        for (int d = 0; d < HD; d++) {
            float4 qf = *(const float4*)&Qs[d * SSTR + i0];
            float4 kf = *(const float4*)&Ks[d * SSTR + j0];
            float qa[4] = {qf.x, qf.y, qf.z, qf.w};
            float kb[4] = {kf.x, kf.y, kf.z, kf.w};
            #pragma unroll
            for (int ii = 0; ii < 4; ii++)
                #pragma unroll
                for (int jj = 0; jj < 4; jj++)
                    sacc[ii][jj] += qa[ii] * kb[jj];
        }
        #pragma unroll
        for (int jj = 0; jj < 4; jj++)
            *(float4*)&Ss[(j0 + jj) * SSTR + i0] =
                make_float4(sacc[0][jj], sacc[1][jj], sacc[2][jj], sacc[3][jj]);
        __syncthreads();

        // Online softmax: 4 lanes per query row
        {
            int i = t >> 2, l = t & 3;
            float mloc = -1e30f;
            #pragma unroll
            for (int s = 0; s < 16; s++)
                mloc = fmaxf(mloc, Ss[(l + s * 4) * SSTR + i]);
            mloc = fmaxf(mloc, __shfl_xor_sync(0xffffffffu, mloc, 1));
            mloc = fmaxf(mloc, __shfl_xor_sync(0xffffffffu, mloc, 2));
            float mold = row_m[i];
            float mnew = fmaxf(mold, mloc);
            float sum = 0.f;
            #pragma unroll
            for (int s = 0; s < 16; s++) {
                int idx = (l + s * 4) * SSTR + i;
                float p = __expf(Ss[idx] - mnew);
                Ss[idx] = p;
                sum += p;
            }
            sum += __shfl_xor_sync(0xffffffffu, sum, 1);
            sum += __shfl_xor_sync(0xffffffffu, sum, 2);
            if (l == 0) {
                float alpha = __expf(mold - mnew);
                row_a[i] = alpha;
                row_m[i] = mnew;
                row_l[i] = row_l[i] * alpha + sum;
            }
        }
        __syncthreads();

        // O = alpha * O + P @ V
        #pragma unroll
        for (int ii = 0; ii < 4; ii++) {
            float a = row_a[i0 + ii];
            #pragma unroll
            for (int jj = 0; jj < 4; jj++) oacc[ii][jj] *= a;
        }
        #pragma unroll 8
        for (int j = 0; j < AT; j++) {
            float4 pf = *(const float4*)&Ss[j * SSTR + i0];
            float4 vf = *(const float4*)&Vs[j * SSTR + j0];
            float pa[4] = {pf.x, pf.y, pf.z, pf.w};
            float vb[4] = {vf.x, vf.y, vf.z, vf.w};
            #pragma unroll
            for (int ii = 0; ii < 4; ii++)
                #pragma unroll
                for (int jj = 0; jj < 4; jj++)
                    oacc[ii][jj] += pa[ii] * vb[jj];
        }
        __syncthreads();
    }

    // Normalize and write
    #pragma unroll
    for (int ii = 0; ii < 4; ii++) {
        float inv = 1.0f / row_l[i0 + ii];
        float4 ov = make_float4(oacc[ii][0] * inv, oacc[ii][1] * inv,
                                oacc[ii][2] * inv, oacc[ii][3] * inv);
        *(float4*)(o + base + (size_t)(m0 + i0 + ii) * Hdim + j0) = ov;
    }
}

// ---------------------------------------------------------------------------
// kernel_launch
// Inputs (metadata order): x, Wq, Wk, Wv, Wo, bo, gamma, beta. Output fp32.
// ---------------------------------------------------------------------------
extern "C" void kernel_launch(void* const* d_in, const int* in_sizes, int n_in,
                              void* d_out, int out_size)
{
    const float* x     = (const float*)d_in[0];
    const float* Wq    = (const float*)d_in[1];
    const float* Wk    = (const float*)d_in[2];
    const float* Wv    = (const float*)d_in[3];
    const float* Wo    = (const float*)d_in[4];
    const float* bo    = (const float*)d_in[5];
    const float* gamma = (const float*)d_in[6];
    const float* beta  = (const float*)d_in[7];
    float* out = (float*)d_out;

    float *xn, *q, *k, *v, *ao;
    cudaGetSymbolAddress((void**)&xn, g_xn);
    cudaGetSymbolAddress((void**)&q,  g_q);
    cudaGetSymbolAddress((void**)&k,  g_k);
    cudaGetSymbolAddress((void**)&v,  g_v);
    cudaGetSymbolAddress((void**)&ao, g_ao);

    // 1) LayerNorm
    ln_kernel<<<Mrows, 256>>>(x, gamma, beta, xn);

    // 2) Q/K/V projections
    dim3 gg(Hdim / BN, Mrows / BM);
    gemm_nt_kernel<<<gg, 256>>>(xn, Wq, q, nullptr, nullptr, Mrows, Hdim, Hdim);
    gemm_nt_kernel<<<gg, 256>>>(xn, Wk, k, nullptr, nullptr, Mrows, Hdim, Hdim);
    gemm_nt_kernel<<<gg, 256>>>(xn, Wv, v, nullptr, nullptr, Mrows, Hdim, Hdim);

    // 3) Attention
    cudaFuncSetAttribute(attn_kernel, cudaFuncAttributeMaxDynamicSharedMemorySize,
                         ATTN_SMEM);
    attn_kernel<<<dim3(Sv / AT, NHEAD, Bv), 256, ATTN_SMEM>>>(q, k, v, ao);

    // 4) Output projection + bias + residual
    gemm_nt_kernel<<<gg, 256>>>(ao, Wo, out, bo, x, Mrows, Hdim, Hdim);
}

// round 9
// speedup vs baseline: 1.5302x; 1.5302x over previous
#include <cuda_runtime.h>
#include <cstdint>
#include <math.h>

// Problem constants
#define Hdim   1024
#define NHEAD  16
#define HD     64
#define Bv     2
#define Sv     2048
#define Mrows  (Bv * Sv)   // 4096
#define EPSLN  1e-5f

// ---------------------------------------------------------------------------
// Device scratch (no cudaMalloc allowed)
// ---------------------------------------------------------------------------
__device__ float g_xn[Mrows * Hdim];
__device__ float g_q [Mrows * Hdim];
__device__ float g_k [Mrows * Hdim];
__device__ float g_v [Mrows * Hdim];
__device__ float g_ao[Mrows * Hdim];

// ---------------------------------------------------------------------------
// PTX helpers (baseline ISA only — NO tcgen05, it doesn't compile on the
// harness's sm_103 (non-'a') target)
// ---------------------------------------------------------------------------
__device__ __forceinline__ uint32_t smem_u32(const void* p) {
    uint32_t a;
    asm("{ .reg .u64 t; cvta.to.shared.u64 t, %1; cvt.u32.u64 %0, t; }"
        : "=r"(a) : "l"(p));
    return a;
}

__device__ __forceinline__ void cp_async16(uint32_t s, const void* g) {
    asm volatile("cp.async.cg.shared.global [%0], [%1], 16;" :: "r"(s), "l"(g));
}
#define CP_COMMIT() asm volatile("cp.async.commit_group;" ::: "memory")
template<int N> __device__ __forceinline__ void cp_wait() {
    asm volatile("cp.async.wait_group %0;" :: "n"(N) : "memory");
}

__device__ __forceinline__ uint32_t f2tf32(float f) {
    uint32_t u;
    asm("cvt.rna.tf32.f32 %0, %1;" : "=r"(u) : "f"(f));
    return u;
}

__device__ __forceinline__ void mma1688(
    float* c, const uint32_t* a, const uint32_t* b)
{
    asm volatile(
        "mma.sync.aligned.m16n8k8.row.col.f32.tf32.tf32.f32 "
        "{%0,%1,%2,%3}, {%4,%5,%6,%7}, {%8,%9}, {%0,%1,%2,%3};"
        : "+f"(c[0]), "+f"(c[1]), "+f"(c[2]), "+f"(c[3])
        : "r"(a[0]), "r"(a[1]), "r"(a[2]), "r"(a[3]), "r"(b[0]), "r"(b[1]));
}

// ---------------------------------------------------------------------------
// LayerNorm: one block per row (1024 cols), 256 threads, float4 per thread
// ---------------------------------------------------------------------------
__global__ __launch_bounds__(256) void ln_kernel(
    const float* __restrict__ x, const float* __restrict__ gamma,
    const float* __restrict__ beta, float* __restrict__ xn)
{
    int row = blockIdx.x;
    int t = threadIdx.x;
    const float* xr = x + (size_t)row * Hdim;
    float4 f = *(const float4*)(xr + t * 4);
    float s  = f.x + f.y + f.z + f.w;
    float s2 = f.x*f.x + f.y*f.y + f.z*f.z + f.w*f.w;

    __shared__ float red[20];
    #pragma unroll
    for (int o = 16; o > 0; o >>= 1) {
        s  += __shfl_down_sync(0xffffffffu, s,  o);
        s2 += __shfl_down_sync(0xffffffffu, s2, o);
    }
    int lane = t & 31, w = t >> 5;
    if (lane == 0) { red[w] = s; red[8 + w] = s2; }
    __syncthreads();
    if (t == 0) {
        float a = 0.f, b = 0.f;
        #pragma unroll
        for (int i = 0; i < 8; i++) { a += red[i]; b += red[8 + i]; }
        float mu  = a * (1.0f / Hdim);
        float var = b * (1.0f / Hdim) - mu * mu;
        red[16] = mu;
        red[17] = rsqrtf(var + EPSLN);
    }
    __syncthreads();
    float mu = red[16], rs = red[17];
    float4 g  = *(const float4*)(gamma + t * 4);
    float4 be = *(const float4*)(beta  + t * 4);
    float4 o;
    o.x = (f.x - mu) * rs * g.x + be.x;
    o.y = (f.y - mu) * rs * g.y + be.y;
    o.z = (f.z - mu) * rs * g.z + be.z;
    o.w = (f.w - mu) * rs * g.w + be.w;
    *(float4*)(xn + (size_t)row * Hdim + t * 4) = o;
}

// ---------------------------------------------------------------------------
// tf32 warp-MMA GEMM (NT): C[m][n] = sum_k A[m][k]*W[n][k] (+bias +resid)
// CTA tile 128x128, BK=32, 256 threads (8 warps in 4x2), double-buffered
// cp.async. Smem stride 36 floats -> conflict-free fragment LDS.
// ---------------------------------------------------------------------------
#define TNKB     32            // 1024 / 32
#define SSTRIDE  36            // floats per smem row (128B data + 16B pad)
#define OPFL     (128 * SSTRIDE)        // floats per operand tile (4608)
#define STAGEFL  (2 * OPFL)             // floats per stage (A+B)
#define GSMEM    (2 * STAGEFL * 4)      // bytes: 73728

__device__ __forceinline__ void load_tile(
    float* smem, int stage, const float* __restrict__ A,
    const float* __restrict__ W, int m0, int n0, int kb, int t)
{
    float* sA = smem + stage * STAGEFL;
    float* sB = sA + OPFL;
    uint32_t aA = smem_u32(sA), aB = smem_u32(sB);
    const float* Ag = A + (size_t)m0 * Hdim + kb * 32;
    const float* Bg = W + (size_t)n0 * Hdim + kb * 32;
    #pragma unroll
    for (int i = 0; i < 4; i++) {
        int c   = t + i * 256;     // 0..1023
        int row = c >> 3;          // 0..127
        int c8  = c & 7;           // 16B chunk within row
        uint32_t so = (uint32_t)(row * (SSTRIDE * 4) + c8 * 16);
        cp_async16(aA + so, Ag + (size_t)row * Hdim + c8 * 4);
        cp_async16(aB + so, Bg + (size_t)row * Hdim + c8 * 4);
    }
    CP_COMMIT();
}

__global__ __launch_bounds__(256, 2) void gemm_mma(
    const float* __restrict__ A, const float* __restrict__ W,
    float* __restrict__ C, const float* __restrict__ bias,
    const float* __restrict__ resid)
{
    extern __shared__ __align__(16) float smem[];
    int t = threadIdx.x, lane = t & 31, wid = t >> 5;
    int n0 = blockIdx.x * 128;
    int m0 = blockIdx.y * 128;
    int wm = wid & 3;       // 0..3 -> 32-row band
    int wn = wid >> 2;      // 0..1 -> 64-col band
    int gid = lane >> 2, qid = lane & 3;

    float acc[2][8][4];
    #pragma unroll
    for (int mi = 0; mi < 2; mi++)
        #pragma unroll
        for (int ni = 0; ni < 8; ni++)
            #pragma unroll
            for (int r = 0; r < 4; r++) acc[mi][ni][r] = 0.f;

    load_tile(smem, 0, A, W, m0, n0, 0, t);
    load_tile(smem, 1, A, W, m0, n0, 1, t);

    for (int kb = 0; kb < TNKB; kb++) {
        int s = kb & 1;
        if (kb < TNKB - 1) cp_wait<1>(); else cp_wait<0>();
        __syncthreads();

        const float* sA = smem + s * STAGEFL;
        const float* sB = sA + OPFL;

        #pragma unroll
        for (int ks = 0; ks < 4; ks++) {
            int k0 = ks * 8;
            uint32_t af[2][4];
            #pragma unroll
            for (int mi = 0; mi < 2; mi++) {
                const float* ap = sA + (wm * 32 + mi * 16 + gid) * SSTRIDE
                                     + k0 + qid;
                af[mi][0] = f2tf32(ap[0]);
                af[mi][1] = f2tf32(ap[8 * SSTRIDE]);
                af[mi][2] = f2tf32(ap[4]);
                af[mi][3] = f2tf32(ap[8 * SSTRIDE + 4]);
            }
            uint32_t bf[8][2];
            #pragma unroll
            for (int ni = 0; ni < 8; ni++) {
                const float* bp = sB + (wn * 64 + ni * 8 + gid) * SSTRIDE
                                     + k0 + qid;
                bf[ni][0] = f2tf32(bp[0]);
                bf[ni][1] = f2tf32(bp[4]);
            }
            #pragma unroll
            for (int mi = 0; mi < 2; mi++)
                #pragma unroll
                for (int ni = 0; ni < 8; ni++)
                    mma1688(acc[mi][ni], af[mi], bf[ni]);
        }
        __syncthreads();
        if (kb + 2 < TNKB)
            load_tile(smem, s, A, W, m0, n0, kb + 2, t);
    }

    // Epilogue: C frag layout: c0,c1 = row gid cols 2q,2q+1; c2,c3 = row gid+8
    #pragma unroll
    for (int mi = 0; mi < 2; mi++) {
        int r0 = m0 + wm * 32 + mi * 16 + gid;
        #pragma unroll
        for (int ni = 0; ni < 8; ni++) {
            int cc = n0 + wn * 64 + ni * 8 + qid * 2;
            float2 o0 = make_float2(acc[mi][ni][0], acc[mi][ni][1]);
            float2 o1 = make_float2(acc[mi][ni][2], acc[mi][ni][3]);
            if (bias) {
                float2 bb = *(const float2*)(bias + cc);
                o0.x += bb.x; o0.y += bb.y;
                o1.x += bb.x; o1.y += bb.y;
            }
            if (resid) {
                float2 ra = *(const float2*)(resid + (size_t)r0 * Hdim + cc);
                float2 rb = *(const float2*)(resid + (size_t)(r0 + 8) * Hdim + cc);
                o0.x += ra.x; o0.y += ra.y;
                o1.x += rb.x; o1.y += rb.y;
            }
            *(float2*)(C + (size_t)r0 * Hdim + cc)       = o0;
            *(float2*)(C + (size_t)(r0 + 8) * Hdim + cc) = o1;
        }
    }
}

// ---------------------------------------------------------------------------
// Flash-style attention: one CTA per (64-query tile, head, batch). (unchanged)
// ---------------------------------------------------------------------------
#define AT   64
#define SSTR 68
#define ATTN_SMEM (4 * 64 * SSTR * 4 + 3 * 64 * 4)

__global__ __launch_bounds__(256) void attn_kernel(
    const float* __restrict__ q, const float* __restrict__ k,
    const float* __restrict__ v, float* __restrict__ o)
{
    extern __shared__ float sm[];
    float* Qs    = sm;
    float* Ks    = Qs + 64 * SSTR;
    float* Vs    = Ks + 64 * SSTR;
    float* Ss    = Vs + 64 * SSTR;
    float* row_m = Ss + 64 * SSTR;
    float* row_l = row_m + 64;
    float* row_a = row_l + 64;

    int t  = threadIdx.x;
    int m0 = blockIdx.x * AT;
    int h  = blockIdx.y;
    int b  = blockIdx.z;
    size_t base = (size_t)b * Sv * Hdim + (size_t)h * HD;

    int r  = t >> 2;
    int d4 = (t & 3) << 4;

    {
        const float* qp = q + base + (size_t)(m0 + r) * Hdim + d4;
        const float sc = 0.125f;
        #pragma unroll
        for (int u = 0; u < 16; u += 4) {
            float4 f = *(const float4*)(qp + u);
            Qs[(d4 + u + 0) * SSTR + r] = f.x * sc;
            Qs[(d4 + u + 1) * SSTR + r] = f.y * sc;
            Qs[(d4 + u + 2) * SSTR + r] = f.z * sc;
            Qs[(d4 + u + 3) * SSTR + r] = f.w * sc;
        }
    }
    if (t < 64) { row_m[t] = -1e30f; row_l[t] = 0.f; }

    int tx = t & 15, ty = t >> 4;
    int i0 = ty * 4, j0 = tx * 4;
    float oacc[4][4];
    #pragma unroll
    for (int ii = 0; ii < 4; ii++)
        #pragma unroll
        for (int jj = 0; jj < 4; jj++) oacc[ii][jj] = 0.f;

    for (int kv0 = 0; kv0 < Sv; kv0 += AT) {
        const float* kp = k + base + (size_t)(kv0 + r) * Hdim + d4;
        const float* vp = v + base + (size_t)(kv0 + r) * Hdim + d4;
        #pragma unroll
        for (int u = 0; u < 16; u += 4) {
            float4 f = *(const float4*)(kp + u);
            Ks[(d4 + u + 0) * SSTR + r] = f.x;
            Ks[(d4 + u + 1) * SSTR + r] = f.y;
            Ks[(d4 + u + 2) * SSTR + r] = f.z;
            Ks[(d4 + u + 3) * SSTR + r] = f.w;
        }
        #pragma unroll
        for (int u = 0; u < 16; u += 4)
            *(float4*)&Vs[r * SSTR + d4 + u] = *(const float4*)(vp + u);
        __syncthreads();

        float sacc[4][4];
        #pragma unroll
        for (int ii = 0; ii < 4; ii++)
            #pragma unroll
            for (int jj = 0; jj < 4; jj++) sacc[ii][jj] = 0.f;
        #pragma unroll 8
        for (int d = 0; d < HD; d++) {
            float4 qf = *(const float4*)&Qs[d * SSTR + i0];
            float4 kf = *(const float4*)&Ks[d * SSTR + j0];
            float qa[4] = {qf.x, qf.y, qf.z, qf.w};
            float kb[4] = {kf.x, kf.y, kf.z, kf.w};
            #pragma unroll
            for (int ii = 0; ii < 4; ii++)
                #pragma unroll
                for (int jj = 0; jj < 4; jj++)
                    sacc[ii][jj] += qa[ii] * kb[jj];
        }
        #pragma unroll
        for (int jj = 0; jj < 4; jj++)
            *(float4*)&Ss[(j0 + jj) * SSTR + i0] =
                make_float4(sacc[0][jj], sacc[1][jj], sacc[2][jj], sacc[3][jj]);
        __syncthreads();

        {
            int i = t >> 2, l = t & 3;
            float mloc = -1e30f;
            #pragma unroll
            for (int s = 0; s < 16; s++)
                mloc = fmaxf(mloc, Ss[(l + s * 4) * SSTR + i]);
            mloc = fmaxf(mloc, __shfl_xor_sync(0xffffffffu, mloc, 1));
            mloc = fmaxf(mloc, __shfl_xor_sync(0xffffffffu, mloc, 2));
            float mold = row_m[i];
            float mnew = fmaxf(mold, mloc);
            float sum = 0.f;
            #pragma unroll
            for (int s = 0; s < 16; s++) {
                int idx = (l + s * 4) * SSTR + i;
                float p = __expf(Ss[idx] - mnew);
                Ss[idx] = p;
                sum += p;
            }
            sum += __shfl_xor_sync(0xffffffffu, sum, 1);
            sum += __shfl_xor_sync(0xffffffffu, sum, 2);
            if (l == 0) {
                float alpha = __expf(mold - mnew);
                row_a[i] = alpha;
                row_m[i] = mnew;
                row_l[i] = row_l[i] * alpha + sum;
            }
        }
        __syncthreads();

        #pragma unroll
        for (int ii = 0; ii < 4; ii++) {
            float a = row_a[i0 + ii];
            #pragma unroll
            for (int jj = 0; jj < 4; jj++) oacc[ii][jj] *= a;
        }
        #pragma unroll 8
        for (int j = 0; j < AT; j++) {
            float4 pf = *(const float4*)&Ss[j * SSTR + i0];
            float4 vf = *(const float4*)&Vs[j * SSTR + j0];
            float pa[4] = {pf.x, pf.y, pf.z, pf.w};
            float vb[4] = {vf.x, vf.y, vf.z, vf.w};
            #pragma unroll
            for (int ii = 0; ii < 4; ii++)
                #pragma unroll
                for (int jj = 0; jj < 4; jj++)
                    oacc[ii][jj] += pa[ii] * vb[jj];
        }
        __syncthreads();
    }

    #pragma unroll
    for (int ii = 0; ii < 4; ii++) {
        float inv = 1.0f / row_l[i0 + ii];
        float4 ov = make_float4(oacc[ii][0] * inv, oacc[ii][1] * inv,
                                oacc[ii][2] * inv, oacc[ii][3] * inv);
        *(float4*)(o + base + (size_t)(m0 + i0 + ii) * Hdim + j0) = ov;
    }
}

// ---------------------------------------------------------------------------
// kernel_launch
// Inputs (metadata order): x, Wq, Wk, Wv, Wo, bo, gamma, beta. Output fp32.
// ---------------------------------------------------------------------------
extern "C" void kernel_launch(void* const* d_in, const int* in_sizes, int n_in,
                              void* d_out, int out_size)
{
    const float* x     = (const float*)d_in[0];
    const float* Wq    = (const float*)d_in[1];
    const float* Wk    = (const float*)d_in[2];
    const float* Wv    = (const float*)d_in[3];
    const float* Wo    = (const float*)d_in[4];
    const float* bo    = (const float*)d_in[5];
    const float* gamma = (const float*)d_in[6];
    const float* beta  = (const float*)d_in[7];
    float* out = (float*)d_out;

    float *xn, *q, *k, *v, *ao;
    cudaGetSymbolAddress((void**)&xn, g_xn);
    cudaGetSymbolAddress((void**)&q,  g_q);
    cudaGetSymbolAddress((void**)&k,  g_k);
    cudaGetSymbolAddress((void**)&v,  g_v);
    cudaGetSymbolAddress((void**)&ao, g_ao);

    cudaFuncSetAttribute(gemm_mma, cudaFuncAttributeMaxDynamicSharedMemorySize,
                         GSMEM);
    cudaFuncSetAttribute(attn_kernel, cudaFuncAttributeMaxDynamicSharedMemorySize,
                         ATTN_SMEM);

    // 1) LayerNorm
    ln_kernel<<<Mrows, 256>>>(x, gamma, beta, xn);

    // 2) Q/K/V projections (tf32 warp MMA)
    dim3 gg(Hdim / 128, Mrows / 128);   // (8, 32)
    gemm_mma<<<gg, 256, GSMEM>>>(xn, Wq, q, nullptr, nullptr);
    gemm_mma<<<gg, 256, GSMEM>>>(xn, Wk, k, nullptr, nullptr);
    gemm_mma<<<gg, 256, GSMEM>>>(xn, Wv, v, nullptr, nullptr);

    // 3) Attention (SIMT flash, unchanged)
    attn_kernel<<<dim3(Sv / AT, NHEAD, Bv), 256, ATTN_SMEM>>>(q, k, v, ao);

    // 4) Output projection + bias + residual (tf32 warp MMA)
    gemm_mma<<<gg, 256, GSMEM>>>(ao, Wo, out, bo, x);
}

// round 10
// speedup vs baseline: 2.1864x; 1.4288x over previous
#include <cuda_runtime.h>
#include <cstdint>
#include <math.h>

// Problem constants
#define Hdim   1024
#define NHEAD  16
#define HD     64
#define Bv     2
#define Sv     2048
#define Mrows  (Bv * Sv)   // 4096
#define EPSLN  1e-5f

// ---------------------------------------------------------------------------
// Device scratch (no cudaMalloc allowed)
// ---------------------------------------------------------------------------
__device__ float g_xn[Mrows * Hdim];
__device__ float g_q [Mrows * Hdim];
__device__ float g_k [Mrows * Hdim];
__device__ float g_v [Mrows * Hdim];
__device__ float g_ao[Mrows * Hdim];

// ---------------------------------------------------------------------------
// PTX helpers (baseline ISA only — NO tcgen05; harness compiles for sm_103
// without the 'a' suffix)
// ---------------------------------------------------------------------------
__device__ __forceinline__ uint32_t smem_u32(const void* p) {
    uint32_t a;
    asm("{ .reg .u64 t; cvta.to.shared.u64 t, %1; cvt.u32.u64 %0, t; }"
        : "=r"(a) : "l"(p));
    return a;
}

__device__ __forceinline__ void cp_async16(uint32_t s, const void* g) {
    asm volatile("cp.async.cg.shared.global [%0], [%1], 16;" :: "r"(s), "l"(g));
}
#define CP_COMMIT() asm volatile("cp.async.commit_group;" ::: "memory")
template<int N> __device__ __forceinline__ void cp_wait() {
    asm volatile("cp.async.wait_group %0;" :: "n"(N) : "memory");
}

__device__ __forceinline__ uint32_t f2tf32(float f) {
    uint32_t u;
    asm("cvt.rna.tf32.f32 %0, %1;" : "=r"(u) : "f"(f));
    return u;
}

__device__ __forceinline__ void mma1688(
    float* c, const uint32_t* a, const uint32_t* b)
{
    asm volatile(
        "mma.sync.aligned.m16n8k8.row.col.f32.tf32.tf32.f32 "
        "{%0,%1,%2,%3}, {%4,%5,%6,%7}, {%8,%9}, {%0,%1,%2,%3};"
        : "+f"(c[0]), "+f"(c[1]), "+f"(c[2]), "+f"(c[3])
        : "r"(a[0]), "r"(a[1]), "r"(a[2]), "r"(a[3]), "r"(b[0]), "r"(b[1]));
}

// ---------------------------------------------------------------------------
// LayerNorm: one block per row (1024 cols), 256 threads, float4 per thread
// ---------------------------------------------------------------------------
__global__ __launch_bounds__(256) void ln_kernel(
    const float* __restrict__ x, const float* __restrict__ gamma,
    const float* __restrict__ beta, float* __restrict__ xn)
{
    int row = blockIdx.x;
    int t = threadIdx.x;
    const float* xr = x + (size_t)row * Hdim;
    float4 f = *(const float4*)(xr + t * 4);
    float s  = f.x + f.y + f.z + f.w;
    float s2 = f.x*f.x + f.y*f.y + f.z*f.z + f.w*f.w;

    __shared__ float red[20];
    #pragma unroll
    for (int o = 16; o > 0; o >>= 1) {
        s  += __shfl_down_sync(0xffffffffu, s,  o);
        s2 += __shfl_down_sync(0xffffffffu, s2, o);
    }
    int lane = t & 31, w = t >> 5;
    if (lane == 0) { red[w] = s; red[8 + w] = s2; }
    __syncthreads();
    if (t == 0) {
        float a = 0.f, b = 0.f;
        #pragma unroll
        for (int i = 0; i < 8; i++) { a += red[i]; b += red[8 + i]; }
        float mu  = a * (1.0f / Hdim);
        float var = b * (1.0f / Hdim) - mu * mu;
        red[16] = mu;
        red[17] = rsqrtf(var + EPSLN);
    }
    __syncthreads();
    float mu = red[16], rs = red[17];
    float4 g  = *(const float4*)(gamma + t * 4);
    float4 be = *(const float4*)(beta  + t * 4);
    float4 o;
    o.x = (f.x - mu) * rs * g.x + be.x;
    o.y = (f.y - mu) * rs * g.y + be.y;
    o.z = (f.z - mu) * rs * g.z + be.z;
    o.w = (f.w - mu) * rs * g.w + be.w;
    *(float4*)(xn + (size_t)row * Hdim + t * 4) = o;
}

// ---------------------------------------------------------------------------
// tf32 warp-MMA GEMM (NT): C[m][n] = sum_k A[m][k]*W[n][k] (+bias +resid)
// CTA tile 128x128, BK=32, 256 threads (8 warps in 4x2), double-buffered
// cp.async. Smem stride 36 floats -> conflict-free fragment LDS.
// rnd=1: round outputs to exact tf32 values (consumed raw by attention mma).
// ---------------------------------------------------------------------------
#define TNKB     32            // 1024 / 32
#define SSTRIDE  36            // floats per smem row (128B data + 16B pad)
#define OPFL     (128 * SSTRIDE)        // floats per operand tile (4608)
#define STAGEFL  (2 * OPFL)             // floats per stage (A+B)
#define GSMEM    (2 * STAGEFL * 4)      // bytes: 73728

__device__ __forceinline__ void load_tile(
    float* smem, int stage, const float* __restrict__ A,
    const float* __restrict__ W, int m0, int n0, int kb, int t)
{
    float* sA = smem + stage * STAGEFL;
    float* sB = sA + OPFL;
    uint32_t aA = smem_u32(sA), aB = smem_u32(sB);
    const float* Ag = A + (size_t)m0 * Hdim + kb * 32;
    const float* Bg = W + (size_t)n0 * Hdim + kb * 32;
    #pragma unroll
    for (int i = 0; i < 4; i++) {
        int c   = t + i * 256;     // 0..1023
        int row = c >> 3;          // 0..127
        int c8  = c & 7;           // 16B chunk within row
        uint32_t so = (uint32_t)(row * (SSTRIDE * 4) + c8 * 16);
        cp_async16(aA + so, Ag + (size_t)row * Hdim + c8 * 4);
        cp_async16(aB + so, Bg + (size_t)row * Hdim + c8 * 4);
    }
    CP_COMMIT();
}

__global__ __launch_bounds__(256, 2) void gemm_mma(
    const float* __restrict__ A, const float* __restrict__ W,
    float* __restrict__ C, const float* __restrict__ bias,
    const float* __restrict__ resid, int rnd)
{
    extern __shared__ __align__(16) float smem[];
    int t = threadIdx.x, lane = t & 31, wid = t >> 5;
    int n0 = blockIdx.x * 128;
    int m0 = blockIdx.y * 128;
    int wm = wid & 3;       // 0..3 -> 32-row band
    int wn = wid >> 2;      // 0..1 -> 64-col band
    int gid = lane >> 2, qid = lane & 3;

    float acc[2][8][4];
    #pragma unroll
    for (int mi = 0; mi < 2; mi++)
        #pragma unroll
        for (int ni = 0; ni < 8; ni++)
            #pragma unroll
            for (int r = 0; r < 4; r++) acc[mi][ni][r] = 0.f;

    load_tile(smem, 0, A, W, m0, n0, 0, t);
    load_tile(smem, 1, A, W, m0, n0, 1, t);

    for (int kb = 0; kb < TNKB; kb++) {
        int s = kb & 1;
        if (kb < TNKB - 1) cp_wait<1>(); else cp_wait<0>();
        __syncthreads();

        const float* sA = smem + s * STAGEFL;
        const float* sB = sA + OPFL;

        #pragma unroll
        for (int ks = 0; ks < 4; ks++) {
            int k0 = ks * 8;
            uint32_t af[2][4];
            #pragma unroll
            for (int mi = 0; mi < 2; mi++) {
                const float* ap = sA + (wm * 32 + mi * 16 + gid) * SSTRIDE
                                     + k0 + qid;
                af[mi][0] = f2tf32(ap[0]);
                af[mi][1] = f2tf32(ap[8 * SSTRIDE]);
                af[mi][2] = f2tf32(ap[4]);
                af[mi][3] = f2tf32(ap[8 * SSTRIDE + 4]);
            }
            uint32_t bf[8][2];
            #pragma unroll
            for (int ni = 0; ni < 8; ni++) {
                const float* bp = sB + (wn * 64 + ni * 8 + gid) * SSTRIDE
                                     + k0 + qid;
                bf[ni][0] = f2tf32(bp[0]);
                bf[ni][1] = f2tf32(bp[4]);
            }
            #pragma unroll
            for (int mi = 0; mi < 2; mi++)
                #pragma unroll
                for (int ni = 0; ni < 8; ni++)
                    mma1688(acc[mi][ni], af[mi], bf[ni]);
        }
        __syncthreads();
        if (kb + 2 < TNKB)
            load_tile(smem, s, A, W, m0, n0, kb + 2, t);
    }

    // Epilogue
    #pragma unroll
    for (int mi = 0; mi < 2; mi++) {
        int r0 = m0 + wm * 32 + mi * 16 + gid;
        #pragma unroll
        for (int ni = 0; ni < 8; ni++) {
            int cc = n0 + wn * 64 + ni * 8 + qid * 2;
            float2 o0 = make_float2(acc[mi][ni][0], acc[mi][ni][1]);
            float2 o1 = make_float2(acc[mi][ni][2], acc[mi][ni][3]);
            if (bias) {
                float2 bb = *(const float2*)(bias + cc);
                o0.x += bb.x; o0.y += bb.y;
                o1.x += bb.x; o1.y += bb.y;
            }
            if (resid) {
                float2 ra = *(const float2*)(resid + (size_t)r0 * Hdim + cc);
                float2 rb = *(const float2*)(resid + (size_t)(r0 + 8) * Hdim + cc);
                o0.x += ra.x; o0.y += ra.y;
                o1.x += rb.x; o1.y += rb.y;
            }
            if (rnd) {
                o0.x = __uint_as_float(f2tf32(o0.x));
                o0.y = __uint_as_float(f2tf32(o0.y));
                o1.x = __uint_as_float(f2tf32(o1.x));
                o1.y = __uint_as_float(f2tf32(o1.y));
            }
            *(float2*)(C + (size_t)r0 * Hdim + cc)       = o0;
            *(float2*)(C + (size_t)(r0 + 8) * Hdim + cc) = o1;
        }
    }
}

// ---------------------------------------------------------------------------
// Flash attention with tf32 warp MMA.
// CTA: 128 queries x (head, batch); 256 threads / 8 warps; warp = 16 q rows.
// KV tiles of 64 keys, double-buffered cp.async. S fragments live in
// registers; softmax via shfl over the qid group; P staged in per-warp smem
// as tf32 bits. Q/K/V arrive pre-rounded to tf32 (rnd=1 GEMMs) -> no cvt in
// the mainloop.
// ---------------------------------------------------------------------------
#define AQ    128
#define AK    64
#define QS    68      // stride for Qs/Ks/Ps (68 mod 32 = 4 -> conflict-free)
#define VSS   72      // stride for Vs       (72 mod 32 = 8 -> conflict-free)
#define KS_FL (64 * QS)    // 4352 floats per K stage
#define VS_FL (64 * VSS)   // 4608 floats per V stage
#define OFF_K (AQ * QS)               // 8704
#define OFF_V (OFF_K + 2 * KS_FL)     // 17408
#define OFF_P (OFF_V + 2 * VS_FL)     // 26624
#define ATTN_SMEM ((OFF_P + AQ * QS) * 4)   // 141312 B

__device__ __forceinline__ void load_kv(
    float* sm, int stage, const float* __restrict__ kg,
    const float* __restrict__ vg, size_t base, int kv0, int t)
{
    uint32_t aK = smem_u32(sm + OFF_K + stage * KS_FL);
    uint32_t aV = smem_u32(sm + OFF_V + stage * VS_FL);
    #pragma unroll
    for (int i = 0; i < 4; i++) {
        int c   = t + i * 256;   // 0..1023
        int row = c >> 4;        // key 0..63
        int c4  = c & 15;        // 16B chunk
        const float* kp = kg + base + (size_t)(kv0 + row) * Hdim + c4 * 4;
        const float* vp = vg + base + (size_t)(kv0 + row) * Hdim + c4 * 4;
        cp_async16(aK + (uint32_t)(row * QS + c4 * 4) * 4, kp);
        cp_async16(aV + (uint32_t)(row * VSS + c4 * 4) * 4, vp);
    }
    CP_COMMIT();
}

__global__ __launch_bounds__(256, 1) void attn_mma(
    const float* __restrict__ q, const float* __restrict__ k,
    const float* __restrict__ v, float* __restrict__ o)
{
    extern __shared__ __align__(16) float sm[];
    uint32_t* Qu = (uint32_t*)sm;
    uint32_t* Ku = (uint32_t*)(sm + OFF_K);
    uint32_t* Vu = (uint32_t*)(sm + OFF_V);
    uint32_t* Pu = (uint32_t*)(sm + OFF_P);

    int t = threadIdx.x, lane = t & 31, wid = t >> 5;
    int gid = lane >> 2, qid = lane & 3;
    int m0 = blockIdx.x * AQ;
    int h  = blockIdx.y, b = blockIdx.z;
    size_t base = (size_t)b * Sv * Hdim + (size_t)h * HD;
    int qrow = wid * 16;

    // Load Q tile scaled by 1/sqrt(HD) (exact power of two -> stays tf32)
    #pragma unroll
    for (int i = 0; i < 8; i++) {
        int c = t + i * 256;     // 0..2047
        int row = c >> 4, c4 = c & 15;
        float4 f = *(const float4*)(q + base + (size_t)(m0 + row) * Hdim + c4 * 4);
        f.x *= 0.125f; f.y *= 0.125f; f.z *= 0.125f; f.w *= 0.125f;
        *(float4*)(sm + row * QS + c4 * 4) = f;
    }

    load_kv(sm, 0, k, v, base, 0, t);
    load_kv(sm, 1, k, v, base, AK, t);

    float oacc[8][4];
    #pragma unroll
    for (int ni = 0; ni < 8; ni++)
        #pragma unroll
        for (int r = 0; r < 4; r++) oacc[ni][r] = 0.f;
    float m1 = -1e30f, m2 = -1e30f, l1 = 0.f, l2 = 0.f;

    for (int it = 0; it < Sv / AK; it++) {
        int s = it & 1;
        if (it < Sv / AK - 1) cp_wait<1>(); else cp_wait<0>();
        __syncthreads();

        // ---- S = Q K^T (scaled) ----
        float sacc[8][4];
        #pragma unroll
        for (int ni = 0; ni < 8; ni++)
            #pragma unroll
            for (int r = 0; r < 4; r++) sacc[ni][r] = 0.f;

        const uint32_t* Kb = Ku + s * KS_FL;
        #pragma unroll
        for (int ks = 0; ks < 8; ks++) {
            int k0 = ks * 8;
            const uint32_t* ap = Qu + (qrow + gid) * QS + k0 + qid;
            uint32_t a[4] = {ap[0], ap[8 * QS], ap[4], ap[8 * QS + 4]};
            #pragma unroll
            for (int ni = 0; ni < 8; ni++) {
                const uint32_t* bp = Kb + (ni * 8 + gid) * QS + k0 + qid;
                uint32_t bb[2] = {bp[0], bp[4]};
                mma1688(sacc[ni], a, bb);
            }
        }

        // ---- online softmax on fragments ----
        float mx1 = -1e30f, mx2 = -1e30f;
        #pragma unroll
        for (int ni = 0; ni < 8; ni++) {
            mx1 = fmaxf(mx1, fmaxf(sacc[ni][0], sacc[ni][1]));
            mx2 = fmaxf(mx2, fmaxf(sacc[ni][2], sacc[ni][3]));
        }
        mx1 = fmaxf(mx1, __shfl_xor_sync(0xffffffffu, mx1, 1));
        mx1 = fmaxf(mx1, __shfl_xor_sync(0xffffffffu, mx1, 2));
        mx2 = fmaxf(mx2, __shfl_xor_sync(0xffffffffu, mx2, 1));
        mx2 = fmaxf(mx2, __shfl_xor_sync(0xffffffffu, mx2, 2));
        float mn1 = fmaxf(m1, mx1), mn2 = fmaxf(m2, mx2);
        float a1 = __expf(m1 - mn1), a2 = __expf(m2 - mn2);
        m1 = mn1; m2 = mn2;

        float ls1 = 0.f, ls2 = 0.f;
        uint32_t* Pw1 = Pu + (qrow + gid) * QS + 2 * qid;
        uint32_t* Pw2 = Pu + (qrow + gid + 8) * QS + 2 * qid;
        #pragma unroll
        for (int ni = 0; ni < 8; ni++) {
            float p0 = __expf(sacc[ni][0] - mn1);
            float p1 = __expf(sacc[ni][1] - mn1);
            float p2 = __expf(sacc[ni][2] - mn2);
            float p3 = __expf(sacc[ni][3] - mn2);
            ls1 += p0 + p1; ls2 += p2 + p3;
            *(uint2*)(Pw1 + ni * 8) = make_uint2(f2tf32(p0), f2tf32(p1));
            *(uint2*)(Pw2 + ni * 8) = make_uint2(f2tf32(p2), f2tf32(p3));
        }
        ls1 += __shfl_xor_sync(0xffffffffu, ls1, 1);
        ls1 += __shfl_xor_sync(0xffffffffu, ls1, 2);
        ls2 += __shfl_xor_sync(0xffffffffu, ls2, 1);
        ls2 += __shfl_xor_sync(0xffffffffu, ls2, 2);
        l1 = l1 * a1 + ls1;
        l2 = l2 * a2 + ls2;

        #pragma unroll
        for (int ni = 0; ni < 8; ni++) {
            oacc[ni][0] *= a1; oacc[ni][1] *= a1;
            oacc[ni][2] *= a2; oacc[ni][3] *= a2;
        }
        __syncwarp();

        // ---- O += P V ----
        const uint32_t* Vb = Vu + s * VS_FL;
        #pragma unroll
        for (int ks = 0; ks < 8; ks++) {
            int k0 = ks * 8;
            const uint32_t* ap = Pu + (qrow + gid) * QS + k0 + qid;
            uint32_t a[4] = {ap[0], ap[8 * QS], ap[4], ap[8 * QS + 4]};
            const uint32_t* vb = Vb + (k0 + qid) * VSS + gid;
            #pragma unroll
            for (int ni = 0; ni < 8; ni++) {
                uint32_t bb[2] = {vb[ni * 8], vb[4 * VSS + ni * 8]};
                mma1688(oacc[ni], a, bb);
            }
        }

        __syncthreads();
        if (it + 2 < Sv / AK)
            load_kv(sm, s, k, v, base, (it + 2) * AK, t);
    }

    // ---- normalize + write ----
    float inv1 = 1.0f / l1, inv2 = 1.0f / l2;
    int r1 = m0 + qrow + gid;
    #pragma unroll
    for (int ni = 0; ni < 8; ni++) {
        int cc = ni * 8 + 2 * qid;
        *(float2*)(o + base + (size_t)r1 * Hdim + cc) =
            make_float2(oacc[ni][0] * inv1, oacc[ni][1] * inv1);
        *(float2*)(o + base + (size_t)(r1 + 8) * Hdim + cc) =
            make_float2(oacc[ni][2] * inv2, oacc[ni][3] * inv2);
    }
}

// ---------------------------------------------------------------------------
// kernel_launch
// Inputs (metadata order): x, Wq, Wk, Wv, Wo, bo, gamma, beta. Output fp32.
// ---------------------------------------------------------------------------
extern "C" void kernel_launch(void* const* d_in, const int* in_sizes, int n_in,
                              void* d_out, int out_size)
{
    const float* x     = (const float*)d_in[0];
    const float* Wq    = (const float*)d_in[1];
    const float* Wk    = (const float*)d_in[2];
    const float* Wv    = (const float*)d_in[3];
    const float* Wo    = (const float*)d_in[4];
    const float* bo    = (const float*)d_in[5];
    const float* gamma = (const float*)d_in[6];
    const float* beta  = (const float*)d_in[7];
    float* out = (float*)d_out;

    float *xn, *q, *k, *v, *ao;
    cudaGetSymbolAddress((void**)&xn, g_xn);
    cudaGetSymbolAddress((void**)&q,  g_q);
    cudaGetSymbolAddress((void**)&k,  g_k);
    cudaGetSymbolAddress((void**)&v,  g_v);
    cudaGetSymbolAddress((void**)&ao, g_ao);

    cudaFuncSetAttribute(gemm_mma, cudaFuncAttributeMaxDynamicSharedMemorySize,
                         GSMEM);
    cudaFuncSetAttribute(attn_mma, cudaFuncAttributeMaxDynamicSharedMemorySize,
                         ATTN_SMEM);

    // 1) LayerNorm
    ln_kernel<<<Mrows, 256>>>(x, gamma, beta, xn);

    // 2) Q/K/V projections (tf32 warp MMA, outputs rounded to exact tf32)
    dim3 gg(Hdim / 128, Mrows / 128);   // (8, 32)
    gemm_mma<<<gg, 256, GSMEM>>>(xn, Wq, q, nullptr, nullptr, 1);
    gemm_mma<<<gg, 256, GSMEM>>>(xn, Wk, k, nullptr, nullptr, 1);
    gemm_mma<<<gg, 256, GSMEM>>>(xn, Wv, v, nullptr, nullptr, 1);

    // 3) Attention (tf32 warp MMA flash)
    attn_mma<<<dim3(Sv / AQ, NHEAD, Bv), 256, ATTN_SMEM>>>(q, k, v, ao);

    // 4) Output projection + bias + residual (full fp32 output)
    gemm_mma<<<gg, 256, GSMEM>>>(ao, Wo, out, bo, x, 0);
}

// round 15
// speedup vs baseline: 3.8160x; 1.7454x over previous
#include <cuda_runtime.h>
#include <cstdint>
#include <math.h>

// Problem constants
#define Hdim   1024
#define NHEAD  16
#define HD     64
#define Bv     2
#define Sv     2048
#define Mrows  (Bv * Sv)   // 4096
#define EPSLN  1e-5f

// ---------------------------------------------------------------------------
// Device scratch (no cudaMalloc allowed)
// ---------------------------------------------------------------------------
__device__ float g_xn[Mrows * Hdim];
__device__ float g_q [Mrows * Hdim];
__device__ float g_k [Mrows * Hdim];
__device__ float g_v [Mrows * Hdim];
__device__ float g_ao[Mrows * Hdim];
__device__ float g_wq[Hdim * Hdim];
__device__ float g_wk[Hdim * Hdim];
__device__ float g_wv[Hdim * Hdim];
__device__ float g_wo[Hdim * Hdim];

// ---------------------------------------------------------------------------
// PTX helpers (baseline ISA only — NO tcgen05; harness compiles for sm_103
// without the 'a' suffix)
// ---------------------------------------------------------------------------
__device__ __forceinline__ uint32_t smem_u32(const void* p) {
    uint32_t a;
    asm("{ .reg .u64 t; cvta.to.shared.u64 t, %1; cvt.u32.u64 %0, t; }"
        : "=r"(a) : "l"(p));
    return a;
}

__device__ __forceinline__ void cp_async16(uint32_t s, const void* g) {
    asm volatile("cp.async.cg.shared.global [%0], [%1], 16;" :: "r"(s), "l"(g));
}
#define CP_COMMIT() asm volatile("cp.async.commit_group;" ::: "memory")
template<int N> __device__ __forceinline__ void cp_wait() {
    asm volatile("cp.async.wait_group %0;" :: "n"(N) : "memory");
}

__device__ __forceinline__ uint32_t f2tf32(float f) {
    uint32_t u;
    asm("cvt.rna.tf32.f32 %0, %1;" : "=r"(u) : "f"(f));
    return u;
}

__device__ __forceinline__ void mma1688(
    float* c, const uint32_t* a, const uint32_t* b)
{
    asm volatile(
        "mma.sync.aligned.m16n8k8.row.col.f32.tf32.tf32.f32 "
        "{%0,%1,%2,%3}, {%4,%5,%6,%7}, {%8,%9}, {%0,%1,%2,%3};"
        : "+f"(c[0]), "+f"(c[1]), "+f"(c[2]), "+f"(c[3])
        : "r"(a[0]), "r"(a[1]), "r"(a[2]), "r"(a[3]), "r"(b[0]), "r"(b[1]));
}

// ---------------------------------------------------------------------------
// Round fp32 array to tf32-exact values (idempotent; mma rounds identically)
// ---------------------------------------------------------------------------
__global__ __launch_bounds__(256) void round_tf32_kernel(
    const float* __restrict__ a, float* __restrict__ b)
{
    int i = (blockIdx.x * 256 + threadIdx.x) * 4;
    float4 f = *(const float4*)(a + i);
    f.x = __uint_as_float(f2tf32(f.x));
    f.y = __uint_as_float(f2tf32(f.y));
    f.z = __uint_as_float(f2tf32(f.z));
    f.w = __uint_as_float(f2tf32(f.w));
    *(float4*)(b + i) = f;
}

// ---------------------------------------------------------------------------
// LayerNorm: one block per row (1024 cols), 256 threads, float4 per thread.
// Output rounded to tf32-exact (feeds QKV mma directly).
// ---------------------------------------------------------------------------
__global__ __launch_bounds__(256) void ln_kernel(
    const float* __restrict__ x, const float* __restrict__ gamma,
    const float* __restrict__ beta, float* __restrict__ xn)
{
    int row = blockIdx.x;
    int t = threadIdx.x;
    const float* xr = x + (size_t)row * Hdim;
    float4 f = *(const float4*)(xr + t * 4);
    float s  = f.x + f.y + f.z + f.w;
    float s2 = f.x*f.x + f.y*f.y + f.z*f.z + f.w*f.w;

    __shared__ float red[20];
    #pragma unroll
    for (int o = 16; o > 0; o >>= 1) {
        s  += __shfl_down_sync(0xffffffffu, s,  o);
        s2 += __shfl_down_sync(0xffffffffu, s2, o);
    }
    int lane = t & 31, w = t >> 5;
    if (lane == 0) { red[w] = s; red[8 + w] = s2; }
    __syncthreads();
    if (t == 0) {
        float a = 0.f, b = 0.f;
        #pragma unroll
        for (int i = 0; i < 8; i++) { a += red[i]; b += red[8 + i]; }
        float mu  = a * (1.0f / Hdim);
        float var = b * (1.0f / Hdim) - mu * mu;
        red[16] = mu;
        red[17] = rsqrtf(var + EPSLN);
    }
    __syncthreads();
    float mu = red[16], rs = red[17];
    float4 g  = *(const float4*)(gamma + t * 4);
    float4 be = *(const float4*)(beta  + t * 4);
    float4 o;
    o.x = __uint_as_float(f2tf32((f.x - mu) * rs * g.x + be.x));
    o.y = __uint_as_float(f2tf32((f.y - mu) * rs * g.y + be.y));
    o.z = __uint_as_float(f2tf32((f.z - mu) * rs * g.z + be.z));
    o.w = __uint_as_float(f2tf32((f.w - mu) * rs * g.w + be.w));
    *(float4*)(xn + (size_t)row * Hdim + t * 4) = o;
}

// ---------------------------------------------------------------------------
// tf32 warp-MMA GEMM (NT): C[m][n] = sum_k A[m][k]*W[n][k] (+bias +resid)
// A and W MUST be tf32-exact (pre-rounded) — mainloop loads raw bits, no cvt.
// CTA tile 128x128, BK=32, 256 threads (8 warps in 4x2), double-buffered
// cp.async. Smem stride 36 floats -> conflict-free fragment LDS.
// rnd=1: round outputs to tf32-exact (consumed raw by attention mma).
// ---------------------------------------------------------------------------
#define TNKB     32            // 1024 / 32
#define SSTRIDE  36            // floats per smem row (128B data + 16B pad)
#define OPFL     (128 * SSTRIDE)        // floats per operand tile (4608)
#define STAGEFL  (2 * OPFL)             // floats per stage (A+B)
#define GSMEM    (2 * STAGEFL * 4)      // bytes: 73728

__device__ __forceinline__ void load_tile(
    float* smem, int stage, const float* __restrict__ A,
    const float* __restrict__ W, int m0, int n0, int kb, int t)
{
    float* sA = smem + stage * STAGEFL;
    float* sB = sA + OPFL;
    uint32_t aA = smem_u32(sA), aB = smem_u32(sB);
    const float* Ag = A + (size_t)m0 * Hdim + kb * 32;
    const float* Bg = W + (size_t)n0 * Hdim + kb * 32;
    #pragma unroll
    for (int i = 0; i < 4; i++) {
        int c   = t + i * 256;     // 0..1023
        int row = c >> 3;          // 0..127
        int c8  = c & 7;           // 16B chunk within row
        uint32_t so = (uint32_t)(row * (SSTRIDE * 4) + c8 * 16);
        cp_async16(aA + so, Ag + (size_t)row * Hdim + c8 * 4);
        cp_async16(aB + so, Bg + (size_t)row * Hdim + c8 * 4);
    }
    CP_COMMIT();
}

__global__ __launch_bounds__(256, 2) void gemm_mma(
    const float* __restrict__ A, const float* __restrict__ W,
    float* __restrict__ C, const float* __restrict__ bias,
    const float* __restrict__ resid, int rnd)
{
    extern __shared__ __align__(16) float smem[];
    int t = threadIdx.x, lane = t & 31, wid = t >> 5;
    int n0 = blockIdx.x * 128;
    int m0 = blockIdx.y * 128;
    int wm = wid & 3;       // 0..3 -> 32-row band
    int wn = wid >> 2;      // 0..1 -> 64-col band
    int gid = lane >> 2, qid = lane & 3;

    float acc[2][8][4];
    #pragma unroll
    for (int mi = 0; mi < 2; mi++)
        #pragma unroll
        for (int ni = 0; ni < 8; ni++)
            #pragma unroll
            for (int r = 0; r < 4; r++) acc[mi][ni][r] = 0.f;

    load_tile(smem, 0, A, W, m0, n0, 0, t);
    load_tile(smem, 1, A, W, m0, n0, 1, t);

    for (int kb = 0; kb < TNKB; kb++) {
        int s = kb & 1;
        if (kb < TNKB - 1) cp_wait<1>(); else cp_wait<0>();
        __syncthreads();

        const uint32_t* sA = (const uint32_t*)(smem + s * STAGEFL);
        const uint32_t* sB = sA + OPFL;

        #pragma unroll
        for (int ks = 0; ks < 4; ks++) {
            int k0 = ks * 8;
            uint32_t af[2][4];
            #pragma unroll
            for (int mi = 0; mi < 2; mi++) {
                const uint32_t* ap = sA + (wm * 32 + mi * 16 + gid) * SSTRIDE
                                        + k0 + qid;
                af[mi][0] = ap[0];
                af[mi][1] = ap[8 * SSTRIDE];
                af[mi][2] = ap[4];
                af[mi][3] = ap[8 * SSTRIDE + 4];
            }
            uint32_t bf[8][2];
            #pragma unroll
            for (int ni = 0; ni < 8; ni++) {
                const uint32_t* bp = sB + (wn * 64 + ni * 8 + gid) * SSTRIDE
                                        + k0 + qid;
                bf[ni][0] = bp[0];
                bf[ni][1] = bp[4];
            }
            #pragma unroll
            for (int mi = 0; mi < 2; mi++)
                #pragma unroll
                for (int ni = 0; ni < 8; ni++)
                    mma1688(acc[mi][ni], af[mi], bf[ni]);
        }
        __syncthreads();
        if (kb + 2 < TNKB)
            load_tile(smem, s, A, W, m0, n0, kb + 2, t);
    }

    // Epilogue
    #pragma unroll
    for (int mi = 0; mi < 2; mi++) {
        int r0 = m0 + wm * 32 + mi * 16 + gid;
        #pragma unroll
        for (int ni = 0; ni < 8; ni++) {
            int cc = n0 + wn * 64 + ni * 8 + qid * 2;
            float2 o0 = make_float2(acc[mi][ni][0], acc[mi][ni][1]);
            float2 o1 = make_float2(acc[mi][ni][2], acc[mi][ni][3]);
            if (bias) {
                float2 bb = *(const float2*)(bias + cc);
                o0.x += bb.x; o0.y += bb.y;
                o1.x += bb.x; o1.y += bb.y;
            }
            if (resid) {
                float2 ra = *(const float2*)(resid + (size_t)r0 * Hdim + cc);
                float2 rb = *(const float2*)(resid + (size_t)(r0 + 8) * Hdim + cc);
                o0.x += ra.x; o0.y += ra.y;
                o1.x += rb.x; o1.y += rb.y;
            }
            if (rnd) {
                o0.x = __uint_as_float(f2tf32(o0.x));
                o0.y = __uint_as_float(f2tf32(o0.y));
                o1.x = __uint_as_float(f2tf32(o1.x));
                o1.y = __uint_as_float(f2tf32(o1.y));
            }
            *(float2*)(C + (size_t)r0 * Hdim + cc)       = o0;
            *(float2*)(C + (size_t)(r0 + 8) * Hdim + cc) = o1;
        }
    }
}

// ---------------------------------------------------------------------------
// Flash attention with tf32 warp MMA.
// CTA: 128 queries x (head, batch); 256 threads / 8 warps; warp = 16 q rows.
// Q fragments live in registers (loaded once); KV tiles of 64 keys,
// double-buffered cp.async; S fragments in registers; softmax via shfl over
// the qid group; P staged in per-warp smem as tf32 bits. Smem 106.4KB ->
// 2 CTAs/SM. Output rounded tf32-exact (feeds Wo mma raw).
// ---------------------------------------------------------------------------
#define AQ    128
#define AK    64
#define QS    68      // stride for Ps/Ks (68 mod 32 = 4 -> conflict-free)
#define VSS   72      // stride for Vs    (72 mod 32 = 8 -> conflict-free)
#define KS_FL (64 * QS)               // 4352 floats per K stage
#define VS_FL (64 * VSS)              // 4608 floats per V stage
#define OFF_K (AQ * QS)               // P region: 128 x QS at offset 0
#define OFF_V (OFF_K + 2 * KS_FL)
#define ATTN_SMEM ((OFF_V + 2 * VS_FL) * 4)   // 106496 B

__device__ __forceinline__ void load_kv(
    float* sm, int stage, const float* __restrict__ kg,
    const float* __restrict__ vg, size_t base, int kv0, int t)
{
    uint32_t aK = smem_u32(sm + OFF_K + stage * KS_FL);
    uint32_t aV = smem_u32(sm + OFF_V + stage * VS_FL);
    #pragma unroll
    for (int i = 0; i < 4; i++) {
        int c   = t + i * 256;   // 0..1023
        int row = c >> 4;        // key 0..63
        int c4  = c & 15;        // 16B chunk
        const float* kp = kg + base + (size_t)(kv0 + row) * Hdim + c4 * 4;
        const float* vp = vg + base + (size_t)(kv0 + row) * Hdim + c4 * 4;
        cp_async16(aK + (uint32_t)(row * QS + c4 * 4) * 4, kp);
        cp_async16(aV + (uint32_t)(row * VSS + c4 * 4) * 4, vp);
    }
    CP_COMMIT();
}

__global__ __launch_bounds__(256, 2) void attn_mma(
    const float* __restrict__ q, const float* __restrict__ k,
    const float* __restrict__ v, float* __restrict__ o)
{
    extern __shared__ __align__(16) float sm[];
    uint32_t* Pu = (uint32_t*)sm;
    uint32_t* Ku = (uint32_t*)(sm + OFF_K);
    uint32_t* Vu = (uint32_t*)(sm + OFF_V);

    int t = threadIdx.x, lane = t & 31, wid = t >> 5;
    int gid = lane >> 2, qid = lane & 3;
    int m0 = blockIdx.x * AQ;
    int h  = blockIdx.y, b = blockIdx.z;
    size_t base = (size_t)b * Sv * Hdim + (size_t)h * HD;
    int qrow = wid * 16;

    load_kv(sm, 0, k, v, base, 0, t);
    load_kv(sm, 1, k, v, base, AK, t);

    // Q fragments in registers: q is tf32-exact; *0.125f preserves mantissa.
    uint32_t qf[8][4];
    {
        const float* qg  = q + base + (size_t)(m0 + qrow + gid) * Hdim;
        const float* qg8 = qg + 8 * Hdim;
        #pragma unroll
        for (int ks = 0; ks < 8; ks++) {
            int k0 = ks * 8;
            qf[ks][0] = __float_as_uint(qg [k0 + qid]     * 0.125f);
            qf[ks][1] = __float_as_uint(qg8[k0 + qid]     * 0.125f);
            qf[ks][2] = __float_as_uint(qg [k0 + qid + 4] * 0.125f);
            qf[ks][3] = __float_as_uint(qg8[k0 + qid + 4] * 0.125f);
        }
    }

    float oacc[8][4];
    #pragma unroll
    for (int ni = 0; ni < 8; ni++)
        #pragma unroll
        for (int r = 0; r < 4; r++) oacc[ni][r] = 0.f;
    float m1 = -1e30f, m2 = -1e30f, l1 = 0.f, l2 = 0.f;

    for (int it = 0; it < Sv / AK; it++) {
        int s = it & 1;
        if (it < Sv / AK - 1) cp_wait<1>(); else cp_wait<0>();
        __syncthreads();

        // ---- S = Q K^T (scaled) ----
        float sacc[8][4];
        #pragma unroll
        for (int ni = 0; ni < 8; ni++)
            #pragma unroll
            for (int r = 0; r < 4; r++) sacc[ni][r] = 0.f;

        const uint32_t* Kb = Ku + s * KS_FL;
        #pragma unroll
        for (int ks = 0; ks < 8; ks++) {
            int k0 = ks * 8;
            #pragma unroll
            for (int ni = 0; ni < 8; ni++) {
                const uint32_t* bp = Kb + (ni * 8 + gid) * QS + k0 + qid;
                uint32_t bb[2] = {bp[0], bp[4]};
                mma1688(sacc[ni], qf[ks], bb);
            }
        }

        // ---- online softmax on fragments ----
        float mx1 = -1e30f, mx2 = -1e30f;
        #pragma unroll
        for (int ni = 0; ni < 8; ni++) {
            mx1 = fmaxf(mx1, fmaxf(sacc[ni][0], sacc[ni][1]));
            mx2 = fmaxf(mx2, fmaxf(sacc[ni][2], sacc[ni][3]));
        }
        mx1 = fmaxf(mx1, __shfl_xor_sync(0xffffffffu, mx1, 1));
        mx1 = fmaxf(mx1, __shfl_xor_sync(0xffffffffu, mx1, 2));
        mx2 = fmaxf(mx2, __shfl_xor_sync(0xffffffffu, mx2, 1));
        mx2 = fmaxf(mx2, __shfl_xor_sync(0xffffffffu, mx2, 2));
        float mn1 = fmaxf(m1, mx1), mn2 = fmaxf(m2, mx2);
        float a1 = __expf(m1 - mn1), a2 = __expf(m2 - mn2);
        m1 = mn1; m2 = mn2;

        float ls1 = 0.f, ls2 = 0.f;
        uint32_t* Pw1 = Pu + (qrow + gid) * QS + 2 * qid;
        uint32_t* Pw2 = Pu + (qrow + gid + 8) * QS + 2 * qid;
        #pragma unroll
        for (int ni = 0; ni < 8; ni++) {
            float p0 = __expf(sacc[ni][0] - mn1);
            float p1 = __expf(sacc[ni][1] - mn1);
            float p2 = __expf(sacc[ni][2] - mn2);
            float p3 = __expf(sacc[ni][3] - mn2);
            ls1 += p0 + p1; ls2 += p2 + p3;
            *(uint2*)(Pw1 + ni * 8) = make_uint2(f2tf32(p0), f2tf32(p1));
            *(uint2*)(Pw2 + ni * 8) = make_uint2(f2tf32(p2), f2tf32(p3));
        }
        ls1 += __shfl_xor_sync(0xffffffffu, ls1, 1);
        ls1 += __shfl_xor_sync(0xffffffffu, ls1, 2);
        ls2 += __shfl_xor_sync(0xffffffffu, ls2, 1);
        ls2 += __shfl_xor_sync(0xffffffffu, ls2, 2);
        l1 = l1 * a1 + ls1;
        l2 = l2 * a2 + ls2;

        #pragma unroll
        for (int ni = 0; ni < 8; ni++) {
            oacc[ni][0] *= a1; oacc[ni][1] *= a1;
            oacc[ni][2] *= a2; oacc[ni][3] *= a2;
        }
        __syncwarp();

        // ---- O += P V ----
        const uint32_t* Vb = Vu + s * VS_FL;
        #pragma unroll
        for (int ks = 0; ks < 8; ks++) {
            int k0 = ks * 8;
            const uint32_t* ap = Pu + (qrow + gid) * QS + k0 + qid;
            uint32_t a[4] = {ap[0], ap[8 * QS], ap[4], ap[8 * QS + 4]};
            const uint32_t* vb = Vb + (k0 + qid) * VSS + gid;
            #pragma unroll
            for (int ni = 0; ni < 8; ni++) {
                uint32_t bb[2] = {vb[ni * 8], vb[4 * VSS + ni * 8]};
                mma1688(oacc[ni], a, bb);
            }
        }

        __syncthreads();
        if (it + 2 < Sv / AK)
            load_kv(sm, s, k, v, base, (it + 2) * AK, t);
    }

    // ---- normalize + write tf32-exact (feeds Wo mma raw) ----
    float inv1 = 1.0f / l1, inv2 = 1.0f / l2;
    int r1 = m0 + qrow + gid;
    #pragma unroll
    for (int ni = 0; ni < 8; ni++) {
        int cc = ni * 8 + 2 * qid;
        *(float2*)(o + base + (size_t)r1 * Hdim + cc) = make_float2(
            __uint_as_float(f2tf32(oacc[ni][0] * inv1)),
            __uint_as_float(f2tf32(oacc[ni][1] * inv1)));
        *(float2*)(o + base + (size_t)(r1 + 8) * Hdim + cc) = make_float2(
            __uint_as_float(f2tf32(oacc[ni][2] * inv2)),
            __uint_as_float(f2tf32(oacc[ni][3] * inv2)));
    }
}

// ---------------------------------------------------------------------------
// kernel_launch
// Inputs (metadata order): x, Wq, Wk, Wv, Wo, bo, gamma, beta. Output fp32.
// ---------------------------------------------------------------------------
extern "C" void kernel_launch(void* const* d_in, const int* in_sizes, int n_in,
                              void* d_out, int out_size)
{
    const float* x     = (const float*)d_in[0];
    const float* Wq    = (const float*)d_in[1];
    const float* Wk    = (const float*)d_in[2];
    const float* Wv    = (const float*)d_in[3];
    const float* Wo    = (const float*)d_in[4];
    const float* bo    = (const float*)d_in[5];
    const float* gamma = (const float*)d_in[6];
    const float* beta  = (const float*)d_in[7];
    float* out = (float*)d_out;

    float *xn, *q, *k, *v, *ao, *wq, *wk, *wv, *wo;
    cudaGetSymbolAddress((void**)&xn, g_xn);
    cudaGetSymbolAddress((void**)&q,  g_q);
    cudaGetSymbolAddress((void**)&k,  g_k);
    cudaGetSymbolAddress((void**)&v,  g_v);
    cudaGetSymbolAddress((void**)&ao, g_ao);
    cudaGetSymbolAddress((void**)&wq, g_wq);
    cudaGetSymbolAddress((void**)&wk, g_wk);
    cudaGetSymbolAddress((void**)&wv, g_wv);
    cudaGetSymbolAddress((void**)&wo, g_wo);

    cudaFuncSetAttribute(gemm_mma, cudaFuncAttributeMaxDynamicSharedMemorySize,
                         GSMEM);
    cudaFuncSetAttribute(attn_mma, cudaFuncAttributeMaxDynamicSharedMemorySize,
                         ATTN_SMEM);

    // 0) Pre-round weights to tf32-exact (removes all mainloop cvts)
    int rb = (Hdim * Hdim) / (256 * 4);   // 1024 blocks
    round_tf32_kernel<<<rb, 256>>>(Wq, wq);
    round_tf32_kernel<<<rb, 256>>>(Wk, wk);
    round_tf32_kernel<<<rb, 256>>>(Wv, wv);
    round_tf32_kernel<<<rb, 256>>>(Wo, wo);

    // 1) LayerNorm (tf32-exact output)
    ln_kernel<<<Mrows, 256>>>(x, gamma, beta, xn);

    // 2) Q/K/V projections (outputs tf32-exact for attention)
    dim3 gg(Hdim / 128, Mrows / 128);   // (8, 32)
    gemm_mma<<<gg, 256, GSMEM>>>(xn, wq, q, nullptr, nullptr, 1);
    gemm_mma<<<gg, 256, GSMEM>>>(xn, wk, k, nullptr, nullptr, 1);
    gemm_mma<<<gg, 256, GSMEM>>>(xn, wv, v, nullptr, nullptr, 1);

    // 3) Attention (tf32 warp MMA flash, 2 CTAs/SM)
    attn_mma<<<dim3(Sv / AQ, NHEAD, Bv), 256, ATTN_SMEM>>>(q, k, v, ao);

    // 4) Output projection + bias + residual (full fp32 output)
    gemm_mma<<<gg, 256, GSMEM>>>(ao, wo, out, bo, x, 0);
}

// round 16
// speedup vs baseline: 7.1629x; 1.8771x over previous
#include <cuda_runtime.h>
#include <cuda_fp16.h>
#include <cstdint>
#include <math.h>

// Problem constants
#define Hdim   1024
#define NHEAD  16
#define HD     64
#define Bv     2
#define Sv     2048
#define Mrows  (Bv * Sv)   // 4096
#define EPSLN  1e-5f

// ---------------------------------------------------------------------------
// Device scratch (no cudaMalloc allowed)
// ---------------------------------------------------------------------------
__device__ __half g_xnh[Mrows * Hdim];
__device__ __half g_qh [Mrows * Hdim];
__device__ __half g_kh [Mrows * Hdim];
__device__ __half g_vh [Mrows * Hdim];
__device__ __half g_aoh[Mrows * Hdim];
__device__ __half g_wqh[Hdim * Hdim];
__device__ __half g_wkh[Hdim * Hdim];
__device__ __half g_wvh[Hdim * Hdim];
__device__ __half g_woh[Hdim * Hdim];

// ---------------------------------------------------------------------------
// PTX helpers (baseline ISA: cp.async, ldmatrix, mma.m16n8k16.f16 — all valid
// on plain sm_103; tcgen05 is NOT)
// ---------------------------------------------------------------------------
__device__ __forceinline__ uint32_t smem_u32(const void* p) {
    uint32_t a;
    asm("{ .reg .u64 t; cvta.to.shared.u64 t, %1; cvt.u32.u64 %0, t; }"
        : "=r"(a) : "l"(p));
    return a;
}

__device__ __forceinline__ void cp_async16(uint32_t s, const void* g) {
    asm volatile("cp.async.cg.shared.global [%0], [%1], 16;" :: "r"(s), "l"(g));
}
#define CP_COMMIT() asm volatile("cp.async.commit_group;" ::: "memory")
template<int N> __device__ __forceinline__ void cp_wait() {
    asm volatile("cp.async.wait_group %0;" :: "n"(N) : "memory");
}

__device__ __forceinline__ void ldmx4(uint32_t* r, uint32_t addr) {
    asm volatile("ldmatrix.sync.aligned.m8n8.x4.shared.b16 {%0,%1,%2,%3}, [%4];"
        : "=r"(r[0]), "=r"(r[1]), "=r"(r[2]), "=r"(r[3]) : "r"(addr));
}
__device__ __forceinline__ void ldmx4t(uint32_t* r, uint32_t addr) {
    asm volatile("ldmatrix.sync.aligned.m8n8.x4.trans.shared.b16 {%0,%1,%2,%3}, [%4];"
        : "=r"(r[0]), "=r"(r[1]), "=r"(r[2]), "=r"(r[3]) : "r"(addr));
}

__device__ __forceinline__ void mma16816(
    float* c, const uint32_t* a, const uint32_t* b)
{
    asm volatile(
        "mma.sync.aligned.m16n8k16.row.col.f32.f16.f16.f32 "
        "{%0,%1,%2,%3}, {%4,%5,%6,%7}, {%8,%9}, {%0,%1,%2,%3};"
        : "+f"(c[0]), "+f"(c[1]), "+f"(c[2]), "+f"(c[3])
        : "r"(a[0]), "r"(a[1]), "r"(a[2]), "r"(a[3]), "r"(b[0]), "r"(b[1]));
}

__device__ __forceinline__ uint32_t packh2(float a, float b) {
    __half2 h = __floats2half2_rn(a, b);
    return *(uint32_t*)&h;
}

// ---------------------------------------------------------------------------
// fp32 -> fp16 conversion (weights)
// ---------------------------------------------------------------------------
__global__ __launch_bounds__(256) void f2h_kernel(
    const float* __restrict__ a, __half* __restrict__ b)
{
    int i = (blockIdx.x * 256 + threadIdx.x) * 8;
    float4 f0 = *(const float4*)(a + i);
    float4 f1 = *(const float4*)(a + i + 4);
    uint4 o;
    o.x = packh2(f0.x, f0.y);
    o.y = packh2(f0.z, f0.w);
    o.z = packh2(f1.x, f1.y);
    o.w = packh2(f1.z, f1.w);
    *(uint4*)(b + i) = o;
}

// ---------------------------------------------------------------------------
// LayerNorm: one block per row, 256 threads, float4 per thread; half output.
// ---------------------------------------------------------------------------
__global__ __launch_bounds__(256) void ln_kernel(
    const float* __restrict__ x, const float* __restrict__ gamma,
    const float* __restrict__ beta, __half* __restrict__ xn)
{
    int row = blockIdx.x;
    int t = threadIdx.x;
    const float* xr = x + (size_t)row * Hdim;
    float4 f = *(const float4*)(xr + t * 4);
    float s  = f.x + f.y + f.z + f.w;
    float s2 = f.x*f.x + f.y*f.y + f.z*f.z + f.w*f.w;

    __shared__ float red[20];
    #pragma unroll
    for (int o = 16; o > 0; o >>= 1) {
        s  += __shfl_down_sync(0xffffffffu, s,  o);
        s2 += __shfl_down_sync(0xffffffffu, s2, o);
    }
    int lane = t & 31, w = t >> 5;
    if (lane == 0) { red[w] = s; red[8 + w] = s2; }
    __syncthreads();
    if (t == 0) {
        float a = 0.f, b = 0.f;
        #pragma unroll
        for (int i = 0; i < 8; i++) { a += red[i]; b += red[8 + i]; }
        float mu  = a * (1.0f / Hdim);
        float var = b * (1.0f / Hdim) - mu * mu;
        red[16] = mu;
        red[17] = rsqrtf(var + EPSLN);
    }
    __syncthreads();
    float mu = red[16], rs = red[17];
    float4 g  = *(const float4*)(gamma + t * 4);
    float4 be = *(const float4*)(beta  + t * 4);
    uint2 o;
    o.x = packh2((f.x - mu) * rs * g.x + be.x, (f.y - mu) * rs * g.y + be.y);
    o.y = packh2((f.z - mu) * rs * g.z + be.z, (f.w - mu) * rs * g.w + be.w);
    *(uint2*)(xn + (size_t)row * Hdim + t * 4) = o;
}

// ---------------------------------------------------------------------------
// fp16 warp-MMA GEMM (NT): C[m][n] = sum_k A[m][k]*W[n][k] (+bias +resid)
// CTA tile 128x128, BK=32, 256 threads (8 warps 4x2), double-buffered
// cp.async, ldmatrix fragment loads. Row pad 16B -> conflict-free.
// Ch != null: half output (QKV). Else: fp32 out + bias + resid (Wo).
// ---------------------------------------------------------------------------
#define HTNKB  32             // 1024 / 32
#define HROWB  80             // bytes per smem row: 64B data + 16B pad (odd 16B units)
#define HOPB   (128 * HROWB)  // 10240 B per operand
#define HSTB   (2 * HOPB)     // 20480 B per stage
#define GSMEMH (2 * HSTB)     // 40960 B

__device__ __forceinline__ void load_tile_h(
    uint32_t sbase, int stage, const __half* __restrict__ A,
    const __half* __restrict__ W, int m0, int n0, int kb, int t)
{
    uint32_t aA = sbase + stage * HSTB;
    uint32_t aB = aA + HOPB;
    const __half* Ag = A + (size_t)m0 * Hdim + kb * 32;
    const __half* Bg = W + (size_t)n0 * Hdim + kb * 32;
    #pragma unroll
    for (int i = 0; i < 2; i++) {
        int c   = t + i * 256;      // 0..511
        int row = c >> 2;           // 0..127
        int ch  = c & 3;            // 16B chunk (8 halves)
        uint32_t off = (uint32_t)(row * HROWB + ch * 16);
        cp_async16(aA + off, Ag + (size_t)row * Hdim + ch * 8);
        cp_async16(aB + off, Bg + (size_t)row * Hdim + ch * 8);
    }
    CP_COMMIT();
}

__global__ __launch_bounds__(256, 2) void gemm_h(
    const __half* __restrict__ A, const __half* __restrict__ W,
    __half* __restrict__ Ch, float* __restrict__ Cf,
    const float* __restrict__ bias, const float* __restrict__ resid)
{
    extern __shared__ __align__(16) char smem[];
    uint32_t sbase = smem_u32(smem);
    int t = threadIdx.x, lane = t & 31, wid = t >> 5;
    int n0 = blockIdx.x * 128;
    int m0 = blockIdx.y * 128;
    int wm = wid & 3;       // 32-row band
    int wn = wid >> 2;      // 64-col band
    int gid = lane >> 2, qid = lane & 3;

    float acc[2][8][4];
    #pragma unroll
    for (int mi = 0; mi < 2; mi++)
        #pragma unroll
        for (int ni = 0; ni < 8; ni++)
            #pragma unroll
            for (int r = 0; r < 4; r++) acc[mi][ni][r] = 0.f;

    load_tile_h(sbase, 0, A, W, m0, n0, 0, t);
    load_tile_h(sbase, 1, A, W, m0, n0, 1, t);

    // ldmatrix per-lane address components
    int a_row = (lane & 15);           // row within 16
    int a_hi  = (lane >> 4) * 16;      // k-chunk byte
    int b_row = ((lane >> 4) & 1) * 8 + (lane & 7);
    int b_hi  = ((lane >> 3) & 1) * 16;

    for (int kb = 0; kb < HTNKB; kb++) {
        int s = kb & 1;
        if (kb < HTNKB - 1) cp_wait<1>(); else cp_wait<0>();
        __syncthreads();

        uint32_t sA = sbase + s * HSTB;
        uint32_t sB = sA + HOPB;

        #pragma unroll
        for (int ks = 0; ks < 2; ks++) {
            uint32_t af[2][4];
            #pragma unroll
            for (int mi = 0; mi < 2; mi++)
                ldmx4(af[mi], sA + (uint32_t)((wm * 32 + mi * 16 + a_row) * HROWB
                                              + ks * 32 + a_hi));
            uint32_t bf[8][2];
            #pragma unroll
            for (int nb = 0; nb < 4; nb++) {
                uint32_t r[4];
                ldmx4(r, sB + (uint32_t)((wn * 64 + nb * 16 + b_row) * HROWB
                                         + ks * 32 + b_hi));
                bf[2 * nb][0] = r[0];     bf[2 * nb][1] = r[1];
                bf[2 * nb + 1][0] = r[2]; bf[2 * nb + 1][1] = r[3];
            }
            #pragma unroll
            for (int mi = 0; mi < 2; mi++)
                #pragma unroll
                for (int ni = 0; ni < 8; ni++)
                    mma16816(acc[mi][ni], af[mi], bf[ni]);
        }
        __syncthreads();
        if (kb + 2 < HTNKB)
            load_tile_h(sbase, s, A, W, m0, n0, kb + 2, t);
    }

    // Epilogue: c0,c1 = row gid cols 2qid,2qid+1; c2,c3 = row gid+8
    #pragma unroll
    for (int mi = 0; mi < 2; mi++) {
        int r0 = m0 + wm * 32 + mi * 16 + gid;
        #pragma unroll
        for (int ni = 0; ni < 8; ni++) {
            int cc = n0 + wn * 64 + ni * 8 + qid * 2;
            if (Ch) {
                *(uint32_t*)(Ch + (size_t)r0 * Hdim + cc) =
                    packh2(acc[mi][ni][0], acc[mi][ni][1]);
                *(uint32_t*)(Ch + (size_t)(r0 + 8) * Hdim + cc) =
                    packh2(acc[mi][ni][2], acc[mi][ni][3]);
            } else {
                float2 o0 = make_float2(acc[mi][ni][0], acc[mi][ni][1]);
                float2 o1 = make_float2(acc[mi][ni][2], acc[mi][ni][3]);
                if (bias) {
                    float2 bb = *(const float2*)(bias + cc);
                    o0.x += bb.x; o0.y += bb.y;
                    o1.x += bb.x; o1.y += bb.y;
                }
                if (resid) {
                    float2 ra = *(const float2*)(resid + (size_t)r0 * Hdim + cc);
                    float2 rb = *(const float2*)(resid + (size_t)(r0 + 8) * Hdim + cc);
                    o0.x += ra.x; o0.y += ra.y;
                    o1.x += rb.x; o1.y += rb.y;
                }
                *(float2*)(Cf + (size_t)r0 * Hdim + cc)       = o0;
                *(float2*)(Cf + (size_t)(r0 + 8) * Hdim + cc) = o1;
            }
        }
    }
}

// ---------------------------------------------------------------------------
// Flash attention, fp16 mma + ldmatrix, FA2 register pipeline.
// CTA: 128 queries x (head, batch); 256 threads / 8 warps; warp = 16 q rows.
// Q fragments from global (once). KV tiles of 64 keys double-buffered.
// S C-frags ARE P A-frags (no smem round trip); V via ldmatrix.trans.
// ---------------------------------------------------------------------------
#define AQ      128
#define AK      64
#define KVROWB  144                 // 128B data + 16B pad (9 x 16B, odd)
#define KVSTB   (64 * KVROWB)       // 9216 B per operand stage
#define OFFVB   (2 * KVSTB)         // V region offset
#define ATTN_SMEMH (4 * KVSTB)      // 36864 B

__device__ __forceinline__ void load_kv_h(
    uint32_t sbase, int stage, const __half* __restrict__ kg,
    const __half* __restrict__ vg, size_t base, int kv0, int t)
{
    uint32_t aK = sbase + stage * KVSTB;
    uint32_t aV = sbase + OFFVB + stage * KVSTB;
    #pragma unroll
    for (int i = 0; i < 2; i++) {
        int c   = t + i * 256;      // 0..511
        int row = c >> 3;           // key 0..63
        int ch  = c & 7;            // 16B chunk (8 halves)
        uint32_t off = (uint32_t)(row * KVROWB + ch * 16);
        cp_async16(aK + off, kg + base + (size_t)(kv0 + row) * Hdim + ch * 8);
        cp_async16(aV + off, vg + base + (size_t)(kv0 + row) * Hdim + ch * 8);
    }
    CP_COMMIT();
}

__global__ __launch_bounds__(256, 2) void attn_h(
    const __half* __restrict__ q, const __half* __restrict__ k,
    const __half* __restrict__ v, __half* __restrict__ o)
{
    extern __shared__ __align__(16) char smc[];
    uint32_t sbase = smem_u32(smc);

    int t = threadIdx.x, lane = t & 31, wid = t >> 5;
    int gid = lane >> 2, qid = lane & 3;
    int m0 = blockIdx.x * AQ;
    int h  = blockIdx.y, b = blockIdx.z;
    size_t base = (size_t)b * Sv * Hdim + (size_t)h * HD;
    int qrow = wid * 16;

    load_kv_h(sbase, 0, k, v, base, 0, t);
    load_kv_h(sbase, 1, k, v, base, AK, t);

    // Q fragments from global, scaled by 1/sqrt(HD) (exact in fp16)
    uint32_t qf[4][4];
    {
        const __half* qg  = q + base + (size_t)(m0 + qrow + gid) * Hdim;
        const __half* qg8 = qg + 8 * Hdim;
        __half2 sc = __float2half2_rn(0.125f);
        #pragma unroll
        for (int ks = 0; ks < 4; ks++) {
            int d0 = ks * 16 + 2 * qid;
            __half2 h0 = __hmul2(*(const __half2*)(qg  + d0),     sc);
            __half2 h1 = __hmul2(*(const __half2*)(qg8 + d0),     sc);
            __half2 h2 = __hmul2(*(const __half2*)(qg  + d0 + 8), sc);
            __half2 h3 = __hmul2(*(const __half2*)(qg8 + d0 + 8), sc);
            qf[ks][0] = *(uint32_t*)&h0;
            qf[ks][1] = *(uint32_t*)&h1;
            qf[ks][2] = *(uint32_t*)&h2;
            qf[ks][3] = *(uint32_t*)&h3;
        }
    }

    float oacc[8][4];
    #pragma unroll
    for (int ni = 0; ni < 8; ni++)
        #pragma unroll
        for (int r = 0; r < 4; r++) oacc[ni][r] = 0.f;
    float m1 = -1e30f, m2 = -1e30f, l1 = 0.f, l2 = 0.f;

    // ldmatrix per-lane address components
    int kb_row = ((lane >> 4) & 1) * 8 + (lane & 7);   // S-phase (K, non-trans)
    int kb_hi  = ((lane >> 3) & 1) * 16;
    int vb_row = (lane & 15);                           // PV-phase (V, trans)
    int vb_hi  = ((lane >> 4) & 1) * 16;

    for (int it = 0; it < Sv / AK; it++) {
        int s = it & 1;
        if (it < Sv / AK - 1) cp_wait<1>(); else cp_wait<0>();
        __syncthreads();

        uint32_t aK = sbase + s * KVSTB;
        uint32_t aV = sbase + OFFVB + s * KVSTB;

        // ---- S = Q K^T ----
        float sacc[8][4];
        #pragma unroll
        for (int ni = 0; ni < 8; ni++)
            #pragma unroll
            for (int r = 0; r < 4; r++) sacc[ni][r] = 0.f;

        #pragma unroll
        for (int ks = 0; ks < 4; ks++) {
            uint32_t bf[8][2];
            #pragma unroll
            for (int nb = 0; nb < 4; nb++) {
                uint32_t r[4];
                ldmx4(r, aK + (uint32_t)((nb * 16 + kb_row) * KVROWB
                                         + ks * 32 + kb_hi));
                bf[2 * nb][0] = r[0];     bf[2 * nb][1] = r[1];
                bf[2 * nb + 1][0] = r[2]; bf[2 * nb + 1][1] = r[3];
            }
            #pragma unroll
            for (int ni = 0; ni < 8; ni++)
                mma16816(sacc[ni], qf[ks], bf[ni]);
        }

        // ---- online softmax on fragments ----
        float mx1 = -1e30f, mx2 = -1e30f;
        #pragma unroll
        for (int ni = 0; ni < 8; ni++) {
            mx1 = fmaxf(mx1, fmaxf(sacc[ni][0], sacc[ni][1]));
            mx2 = fmaxf(mx2, fmaxf(sacc[ni][2], sacc[ni][3]));
        }
        mx1 = fmaxf(mx1, __shfl_xor_sync(0xffffffffu, mx1, 1));
        mx1 = fmaxf(mx1, __shfl_xor_sync(0xffffffffu, mx1, 2));
        mx2 = fmaxf(mx2, __shfl_xor_sync(0xffffffffu, mx2, 1));
        mx2 = fmaxf(mx2, __shfl_xor_sync(0xffffffffu, mx2, 2));
        float mn1 = fmaxf(m1, mx1), mn2 = fmaxf(m2, mx2);
        float a1 = __expf(m1 - mn1), a2 = __expf(m2 - mn2);
        m1 = mn1; m2 = mn2;

        // P fragments: S C-frag layout == A-frag layout for m16n8k16
        uint32_t ph[8][2];
        float ls1 = 0.f, ls2 = 0.f;
        #pragma unroll
        for (int ni = 0; ni < 8; ni++) {
            float p0 = __expf(sacc[ni][0] - mn1);
            float p1 = __expf(sacc[ni][1] - mn1);
            float p2 = __expf(sacc[ni][2] - mn2);
            float p3 = __expf(sacc[ni][3] - mn2);
            ls1 += p0 + p1; ls2 += p2 + p3;
            ph[ni][0] = packh2(p0, p1);
            ph[ni][1] = packh2(p2, p3);
        }
        ls1 += __shfl_xor_sync(0xffffffffu, ls1, 1);
        ls1 += __shfl_xor_sync(0xffffffffu, ls1, 2);
        ls2 += __shfl_xor_sync(0xffffffffu, ls2, 1);
        ls2 += __shfl_xor_sync(0xffffffffu, ls2, 2);
        l1 = l1 * a1 + ls1;
        l2 = l2 * a2 + ls2;

        #pragma unroll
        for (int ni = 0; ni < 8; ni++) {
            oacc[ni][0] *= a1; oacc[ni][1] *= a1;
            oacc[ni][2] *= a2; oacc[ni][3] *= a2;
        }

        // ---- O += P V ----
        #pragma unroll
        for (int ks = 0; ks < 4; ks++) {
            uint32_t vb[8][2];
            #pragma unroll
            for (int nb = 0; nb < 4; nb++) {
                uint32_t r[4];
                ldmx4t(r, aV + (uint32_t)((16 * ks + vb_row) * KVROWB
                                          + nb * 32 + vb_hi));
                vb[2 * nb][0] = r[0];     vb[2 * nb][1] = r[1];
                vb[2 * nb + 1][0] = r[2]; vb[2 * nb + 1][1] = r[3];
            }
            uint32_t a[4] = {ph[2 * ks][0], ph[2 * ks][1],
                             ph[2 * ks + 1][0], ph[2 * ks + 1][1]};
            #pragma unroll
            for (int ni = 0; ni < 8; ni++)
                mma16816(oacc[ni], a, vb[ni]);
        }

        __syncthreads();
        if (it + 2 < Sv / AK)
            load_kv_h(sbase, s, k, v, base, (it + 2) * AK, t);
    }

    // ---- normalize + write half ----
    float inv1 = 1.0f / l1, inv2 = 1.0f / l2;
    int r1 = m0 + qrow + gid;
    #pragma unroll
    for (int ni = 0; ni < 8; ni++) {
        int cc = ni * 8 + 2 * qid;
        *(uint32_t*)(o + base + (size_t)r1 * Hdim + cc) =
            packh2(oacc[ni][0] * inv1, oacc[ni][1] * inv1);
        *(uint32_t*)(o + base + (size_t)(r1 + 8) * Hdim + cc) =
            packh2(oacc[ni][2] * inv2, oacc[ni][3] * inv2);
    }
}

// ---------------------------------------------------------------------------
// kernel_launch
// Inputs (metadata order): x, Wq, Wk, Wv, Wo, bo, gamma, beta. Output fp32.
// ---------------------------------------------------------------------------
extern "C" void kernel_launch(void* const* d_in, const int* in_sizes, int n_in,
                              void* d_out, int out_size)
{
    const float* x     = (const float*)d_in[0];
    const float* Wq    = (const float*)d_in[1];
    const float* Wk    = (const float*)d_in[2];
    const float* Wv    = (const float*)d_in[3];
    const float* Wo    = (const float*)d_in[4];
    const float* bo    = (const float*)d_in[5];
    const float* gamma = (const float*)d_in[6];
    const float* beta  = (const float*)d_in[7];
    float* out = (float*)d_out;

    __half *xn, *q, *k, *v, *ao, *wq, *wk, *wv, *wo;
    cudaGetSymbolAddress((void**)&xn, g_xnh);
    cudaGetSymbolAddress((void**)&q,  g_qh);
    cudaGetSymbolAddress((void**)&k,  g_kh);
    cudaGetSymbolAddress((void**)&v,  g_vh);
    cudaGetSymbolAddress((void**)&ao, g_aoh);
    cudaGetSymbolAddress((void**)&wq, g_wqh);
    cudaGetSymbolAddress((void**)&wk, g_wkh);
    cudaGetSymbolAddress((void**)&wv, g_wvh);
    cudaGetSymbolAddress((void**)&wo, g_woh);

    cudaFuncSetAttribute(gemm_h, cudaFuncAttributeMaxDynamicSharedMemorySize,
                         GSMEMH);
    cudaFuncSetAttribute(attn_h, cudaFuncAttributeMaxDynamicSharedMemorySize,
                         ATTN_SMEMH);

    // 0) Convert weights to fp16
    int cb = (Hdim * Hdim) / (256 * 8);   // 512 blocks
    f2h_kernel<<<cb, 256>>>(Wq, wq);
    f2h_kernel<<<cb, 256>>>(Wk, wk);
    f2h_kernel<<<cb, 256>>>(Wv, wv);
    f2h_kernel<<<cb, 256>>>(Wo, wo);

    // 1) LayerNorm (fp16 output)
    ln_kernel<<<Mrows, 256>>>(x, gamma, beta, xn);

    // 2) Q/K/V projections (fp16 in/out, fp32 accum)
    dim3 gg(Hdim / 128, Mrows / 128);   // (8, 32)
    gemm_h<<<gg, 256, GSMEMH>>>(xn, wq, q, nullptr, nullptr, nullptr);
    gemm_h<<<gg, 256, GSMEMH>>>(xn, wk, k, nullptr, nullptr, nullptr);
    gemm_h<<<gg, 256, GSMEMH>>>(xn, wv, v, nullptr, nullptr, nullptr);

    // 3) Attention (fp16 mma flash, FA2 register pipeline)
    attn_h<<<dim3(Sv / AQ, NHEAD, Bv), 256, ATTN_SMEMH>>>(q, k, v, ao);

    // 4) Output projection + bias + residual (fp32 output)
    gemm_h<<<gg, 256, GSMEMH>>>(ao, wo, nullptr, out, bo, x);
}

// round 17
// speedup vs baseline: 7.8913x; 1.1017x over previous
#include <cuda_runtime.h>
#include <cuda_fp16.h>
#include <cstdint>
#include <math.h>

// Problem constants
#define Hdim   1024
#define NHEAD  16
#define HD     64
#define Bv     2
#define Sv     2048
#define Mrows  (Bv * Sv)   // 4096
#define EPSLN  1e-5f

// ---------------------------------------------------------------------------
// Device scratch (no cudaMalloc allowed)
// ---------------------------------------------------------------------------
__device__ __half g_xnh[Mrows * Hdim];
__device__ __half g_qh [Mrows * Hdim];
__device__ __half g_kh [Mrows * Hdim];
__device__ __half g_vh [Mrows * Hdim];
__device__ __half g_aoh[Mrows * Hdim];
__device__ __half g_wqh[Hdim * Hdim];
__device__ __half g_wkh[Hdim * Hdim];
__device__ __half g_wvh[Hdim * Hdim];
__device__ __half g_woh[Hdim * Hdim];

// ---------------------------------------------------------------------------
// PTX helpers (baseline ISA: cp.async, ldmatrix, mma.m16n8k16.f16 — all valid
// on plain sm_103; tcgen05 is NOT)
// ---------------------------------------------------------------------------
__device__ __forceinline__ uint32_t smem_u32(const void* p) {
    uint32_t a;
    asm("{ .reg .u64 t; cvta.to.shared.u64 t, %1; cvt.u32.u64 %0, t; }"
        : "=r"(a) : "l"(p));
    return a;
}

__device__ __forceinline__ void cp_async16(uint32_t s, const void* g) {
    asm volatile("cp.async.cg.shared.global [%0], [%1], 16;" :: "r"(s), "l"(g));
}
#define CP_COMMIT() asm volatile("cp.async.commit_group;" ::: "memory")
template<int N> __device__ __forceinline__ void cp_wait() {
    asm volatile("cp.async.wait_group %0;" :: "n"(N) : "memory");
}

__device__ __forceinline__ void ldmx4(uint32_t* r, uint32_t addr) {
    asm volatile("ldmatrix.sync.aligned.m8n8.x4.shared.b16 {%0,%1,%2,%3}, [%4];"
        : "=r"(r[0]), "=r"(r[1]), "=r"(r[2]), "=r"(r[3]) : "r"(addr));
}
__device__ __forceinline__ void ldmx4t(uint32_t* r, uint32_t addr) {
    asm volatile("ldmatrix.sync.aligned.m8n8.x4.trans.shared.b16 {%0,%1,%2,%3}, [%4];"
        : "=r"(r[0]), "=r"(r[1]), "=r"(r[2]), "=r"(r[3]) : "r"(addr));
}

__device__ __forceinline__ void mma16816(
    float* c, const uint32_t* a, const uint32_t* b)
{
    asm volatile(
        "mma.sync.aligned.m16n8k16.row.col.f32.f16.f16.f32 "
        "{%0,%1,%2,%3}, {%4,%5,%6,%7}, {%8,%9}, {%0,%1,%2,%3};"
        : "+f"(c[0]), "+f"(c[1]), "+f"(c[2]), "+f"(c[3])
        : "r"(a[0]), "r"(a[1]), "r"(a[2]), "r"(a[3]), "r"(b[0]), "r"(b[1]));
}

__device__ __forceinline__ uint32_t packh2(float a, float b) {
    __half2 h = __floats2half2_rn(a, b);
    return *(uint32_t*)&h;
}

// ---------------------------------------------------------------------------
// Fused fp32 -> fp16 conversion of all four weight matrices.
// grid (512, 4): 2048 blocks -> enough parallelism to hide DRAM latency.
// ---------------------------------------------------------------------------
__global__ __launch_bounds__(256) void f2h4_kernel(
    const float* __restrict__ a0, const float* __restrict__ a1,
    const float* __restrict__ a2, const float* __restrict__ a3,
    __half* __restrict__ b0, __half* __restrict__ b1,
    __half* __restrict__ b2, __half* __restrict__ b3)
{
    int w = blockIdx.y;
    const float* a = (w == 0) ? a0 : (w == 1) ? a1 : (w == 2) ? a2 : a3;
    __half*      b = (w == 0) ? b0 : (w == 1) ? b1 : (w == 2) ? b2 : b3;
    int i = (blockIdx.x * 256 + threadIdx.x) * 8;
    float4 f0 = *(const float4*)(a + i);
    float4 f1 = *(const float4*)(a + i + 4);
    uint4 o;
    o.x = packh2(f0.x, f0.y);
    o.y = packh2(f0.z, f0.w);
    o.z = packh2(f1.x, f1.y);
    o.w = packh2(f1.z, f1.w);
    *(uint4*)(b + i) = o;
}

// ---------------------------------------------------------------------------
// LayerNorm: one block per row, 256 threads, float4 per thread; half output.
// ---------------------------------------------------------------------------
__global__ __launch_bounds__(256) void ln_kernel(
    const float* __restrict__ x, const float* __restrict__ gamma,
    const float* __restrict__ beta, __half* __restrict__ xn)
{
    int row = blockIdx.x;
    int t = threadIdx.x;
    const float* xr = x + (size_t)row * Hdim;
    float4 f = *(const float4*)(xr + t * 4);
    float s  = f.x + f.y + f.z + f.w;
    float s2 = f.x*f.x + f.y*f.y + f.z*f.z + f.w*f.w;

    __shared__ float red[20];
    #pragma unroll
    for (int o = 16; o > 0; o >>= 1) {
        s  += __shfl_down_sync(0xffffffffu, s,  o);
        s2 += __shfl_down_sync(0xffffffffu, s2, o);
    }
    int lane = t & 31, w = t >> 5;
    if (lane == 0) { red[w] = s; red[8 + w] = s2; }
    __syncthreads();
    if (t == 0) {
        float a = 0.f, b = 0.f;
        #pragma unroll
        for (int i = 0; i < 8; i++) { a += red[i]; b += red[8 + i]; }
        float mu  = a * (1.0f / Hdim);
        float var = b * (1.0f / Hdim) - mu * mu;
        red[16] = mu;
        red[17] = rsqrtf(var + EPSLN);
    }
    __syncthreads();
    float mu = red[16], rs = red[17];
    float4 g  = *(const float4*)(gamma + t * 4);
    float4 be = *(const float4*)(beta  + t * 4);
    uint2 o;
    o.x = packh2((f.x - mu) * rs * g.x + be.x, (f.y - mu) * rs * g.y + be.y);
    o.y = packh2((f.z - mu) * rs * g.z + be.z, (f.w - mu) * rs * g.w + be.w);
    *(uint2*)(xn + (size_t)row * Hdim + t * 4) = o;
}

// ---------------------------------------------------------------------------
// fp16 warp-MMA GEMM body (NT): C[m][n] = sum_k A[m][k]*W[n][k] (+bias+resid)
// CTA tile 128x128, BK=32, 256 threads (8 warps 4x2), 3-stage cp.async
// pipeline with ONE __syncthreads per K-iteration; ldmatrix fragment loads.
// ---------------------------------------------------------------------------
#define HTNKB  32             // 1024 / 32
#define HROWB  80             // bytes per smem row: 64B data + 16B pad
#define HOPB   (128 * HROWB)  // 10240 B per operand
#define HSTB   (2 * HOPB)     // 20480 B per stage
#define GSTAGE 3
#define GSMEMH (GSTAGE * HSTB)   // 61440 B

__device__ __forceinline__ void load_tile_h(
    uint32_t sbase, int stage, const __half* __restrict__ A,
    const __half* __restrict__ W, int m0, int n0, int kb, int t)
{
    uint32_t aA = sbase + stage * HSTB;
    uint32_t aB = aA + HOPB;
    const __half* Ag = A + (size_t)m0 * Hdim + kb * 32;
    const __half* Bg = W + (size_t)n0 * Hdim + kb * 32;
    #pragma unroll
    for (int i = 0; i < 2; i++) {
        int c   = t + i * 256;      // 0..511
        int row = c >> 2;           // 0..127
        int ch  = c & 3;            // 16B chunk (8 halves)
        uint32_t off = (uint32_t)(row * HROWB + ch * 16);
        cp_async16(aA + off, Ag + (size_t)row * Hdim + ch * 8);
        cp_async16(aB + off, Bg + (size_t)row * Hdim + ch * 8);
    }
    CP_COMMIT();
}

__device__ __forceinline__ void gemm_body(
    const __half* __restrict__ A, const __half* __restrict__ W,
    __half* __restrict__ Ch, float* __restrict__ Cf,
    const float* __restrict__ bias, const float* __restrict__ resid,
    uint32_t sbase)
{
    int t = threadIdx.x, lane = t & 31, wid = t >> 5;
    int n0 = blockIdx.x * 128;
    int m0 = blockIdx.y * 128;
    int wm = wid & 3;       // 32-row band
    int wn = wid >> 2;      // 64-col band
    int gid = lane >> 2, qid = lane & 3;

    float acc[2][8][4];
    #pragma unroll
    for (int mi = 0; mi < 2; mi++)
        #pragma unroll
        for (int ni = 0; ni < 8; ni++)
            #pragma unroll
            for (int r = 0; r < 4; r++) acc[mi][ni][r] = 0.f;

    load_tile_h(sbase, 0, A, W, m0, n0, 0, t);
    load_tile_h(sbase, 1, A, W, m0, n0, 1, t);

    int a_row = (lane & 15);
    int a_hi  = (lane >> 4) * 16;
    int b_row = ((lane >> 4) & 1) * 8 + (lane & 7);
    int b_hi  = ((lane >> 3) & 1) * 16;

    for (int kb = 0; kb < HTNKB; kb++) {
        int s = kb % GSTAGE;
        if (kb < HTNKB - 1) cp_wait<1>(); else cp_wait<0>();
        __syncthreads();
        // Prefetch stage kb+2 (its buffer was consumed at kb-1; safe after sync)
        if (kb + 2 < HTNKB)
            load_tile_h(sbase, (kb + 2) % GSTAGE, A, W, m0, n0, kb + 2, t);

        uint32_t sA = sbase + s * HSTB;
        uint32_t sB = sA + HOPB;

        #pragma unroll
        for (int ks = 0; ks < 2; ks++) {
            uint32_t af[2][4];
            #pragma unroll
            for (int mi = 0; mi < 2; mi++)
                ldmx4(af[mi], sA + (uint32_t)((wm * 32 + mi * 16 + a_row) * HROWB
                                              + ks * 32 + a_hi));
            uint32_t bf[8][2];
            #pragma unroll
            for (int nb = 0; nb < 4; nb++) {
                uint32_t r[4];
                ldmx4(r, sB + (uint32_t)((wn * 64 + nb * 16 + b_row) * HROWB
                                         + ks * 32 + b_hi));
                bf[2 * nb][0] = r[0];     bf[2 * nb][1] = r[1];
                bf[2 * nb + 1][0] = r[2]; bf[2 * nb + 1][1] = r[3];
            }
            #pragma unroll
            for (int mi = 0; mi < 2; mi++)
                #pragma unroll
                for (int ni = 0; ni < 8; ni++)
                    mma16816(acc[mi][ni], af[mi], bf[ni]);
        }
    }

    // Epilogue: c0,c1 = row gid cols 2qid,2qid+1; c2,c3 = row gid+8
    #pragma unroll
    for (int mi = 0; mi < 2; mi++) {
        int r0 = m0 + wm * 32 + mi * 16 + gid;
        #pragma unroll
        for (int ni = 0; ni < 8; ni++) {
            int cc = n0 + wn * 64 + ni * 8 + qid * 2;
            if (Ch) {
                *(uint32_t*)(Ch + (size_t)r0 * Hdim + cc) =
                    packh2(acc[mi][ni][0], acc[mi][ni][1]);
                *(uint32_t*)(Ch + (size_t)(r0 + 8) * Hdim + cc) =
                    packh2(acc[mi][ni][2], acc[mi][ni][3]);
            } else {
                float2 o0 = make_float2(acc[mi][ni][0], acc[mi][ni][1]);
                float2 o1 = make_float2(acc[mi][ni][2], acc[mi][ni][3]);
                if (bias) {
                    float2 bb = *(const float2*)(bias + cc);
                    o0.x += bb.x; o0.y += bb.y;
                    o1.x += bb.x; o1.y += bb.y;
                }
                if (resid) {
                    float2 ra = *(const float2*)(resid + (size_t)r0 * Hdim + cc);
                    float2 rb = *(const float2*)(resid + (size_t)(r0 + 8) * Hdim + cc);
                    o0.x += ra.x; o0.y += ra.y;
                    o1.x += rb.x; o1.y += rb.y;
                }
                *(float2*)(Cf + (size_t)r0 * Hdim + cc)       = o0;
                *(float2*)(Cf + (size_t)(r0 + 8) * Hdim + cc) = o1;
            }
        }
    }
}

// Fused QKV: one launch, blockIdx.z selects (W, C) pair. 768 CTAs.
__global__ __launch_bounds__(256, 2) void gemm_qkv(
    const __half* __restrict__ A,
    const __half* __restrict__ w0, const __half* __restrict__ w1,
    const __half* __restrict__ w2,
    __half* __restrict__ c0, __half* __restrict__ c1, __half* __restrict__ c2)
{
    extern __shared__ __align__(16) char smem[];
    int z = blockIdx.z;
    const __half* W = (z == 0) ? w0 : (z == 1) ? w1 : w2;
    __half*       C = (z == 0) ? c0 : (z == 1) ? c1 : c2;
    gemm_body(A, W, C, nullptr, nullptr, nullptr, smem_u32(smem));
}

// Wo projection: fp32 output + bias + residual.
__global__ __launch_bounds__(256, 2) void gemm_wo(
    const __half* __restrict__ A, const __half* __restrict__ W,
    float* __restrict__ Cf, const float* __restrict__ bias,
    const float* __restrict__ resid)
{
    extern __shared__ __align__(16) char smem[];
    gemm_body(A, W, nullptr, Cf, bias, resid, smem_u32(smem));
}

// ---------------------------------------------------------------------------
// Flash attention, fp16 mma + ldmatrix, FA2 register pipeline.
// CTA: 128 queries x (head, batch); 256 threads / 8 warps; warp = 16 q rows.
// KV tiles of 64 keys, 3-stage cp.async pipeline, ONE sync per tile.
// S C-frags ARE P A-frags (no smem round trip); V via ldmatrix.trans.
// ---------------------------------------------------------------------------
#define AQ      128
#define AK      64
#define KVROWB  144                 // 128B data + 16B pad
#define KVSTB   (64 * KVROWB)       // 9216 B per operand stage
#define ASTAGE  3
#define OFFVB   (ASTAGE * KVSTB)    // V region offset
#define ATTN_SMEMH (2 * ASTAGE * KVSTB)   // 55296 B

__device__ __forceinline__ void load_kv_h(
    uint32_t sbase, int stage, const __half* __restrict__ kg,
    const __half* __restrict__ vg, size_t base, int kv0, int t)
{
    uint32_t aK = sbase + stage * KVSTB;
    uint32_t aV = sbase + OFFVB + stage * KVSTB;
    #pragma unroll
    for (int i = 0; i < 2; i++) {
        int c   = t + i * 256;      // 0..511
        int row = c >> 3;           // key 0..63
        int ch  = c & 7;            // 16B chunk (8 halves)
        uint32_t off = (uint32_t)(row * KVROWB + ch * 16);
        cp_async16(aK + off, kg + base + (size_t)(kv0 + row) * Hdim + ch * 8);
        cp_async16(aV + off, vg + base + (size_t)(kv0 + row) * Hdim + ch * 8);
    }
    CP_COMMIT();
}

__global__ __launch_bounds__(256, 2) void attn_h(
    const __half* __restrict__ q, const __half* __restrict__ k,
    const __half* __restrict__ v, __half* __restrict__ o)
{
    extern __shared__ __align__(16) char smc[];
    uint32_t sbase = smem_u32(smc);

    int t = threadIdx.x, lane = t & 31, wid = t >> 5;
    int gid = lane >> 2, qid = lane & 3;
    int m0 = blockIdx.x * AQ;
    int h  = blockIdx.y, b = blockIdx.z;
    size_t base = (size_t)b * Sv * Hdim + (size_t)h * HD;
    int qrow = wid * 16;

    load_kv_h(sbase, 0, k, v, base, 0, t);
    load_kv_h(sbase, 1, k, v, base, AK, t);

    // Q fragments from global, scaled by 1/sqrt(HD) (exact in fp16)
    uint32_t qf[4][4];
    {
        const __half* qg  = q + base + (size_t)(m0 + qrow + gid) * Hdim;
        const __half* qg8 = qg + 8 * Hdim;
        __half2 sc = __float2half2_rn(0.125f);
        #pragma unroll
        for (int ks = 0; ks < 4; ks++) {
            int d0 = ks * 16 + 2 * qid;
            __half2 h0 = __hmul2(*(const __half2*)(qg  + d0),     sc);
            __half2 h1 = __hmul2(*(const __half2*)(qg8 + d0),     sc);
            __half2 h2 = __hmul2(*(const __half2*)(qg  + d0 + 8), sc);
            __half2 h3 = __hmul2(*(const __half2*)(qg8 + d0 + 8), sc);
            qf[ks][0] = *(uint32_t*)&h0;
            qf[ks][1] = *(uint32_t*)&h1;
            qf[ks][2] = *(uint32_t*)&h2;
            qf[ks][3] = *(uint32_t*)&h3;
        }
    }

    float oacc[8][4];
    #pragma unroll
    for (int ni = 0; ni < 8; ni++)
        #pragma unroll
        for (int r = 0; r < 4; r++) oacc[ni][r] = 0.f;
    float m1 = -1e30f, m2 = -1e30f, l1 = 0.f, l2 = 0.f;

    int kb_row = ((lane >> 4) & 1) * 8 + (lane & 7);   // S-phase (K, non-trans)
    int kb_hi  = ((lane >> 3) & 1) * 16;
    int vb_row = (lane & 15);                           // PV-phase (V, trans)
    int vb_hi  = ((lane >> 4) & 1) * 16;

    for (int it = 0; it < Sv / AK; it++) {
        int s = it % ASTAGE;
        if (it < Sv / AK - 1) cp_wait<1>(); else cp_wait<0>();
        __syncthreads();
        // Prefetch stage it+2 (buffer consumed at it-1; safe after sync)
        if (it + 2 < Sv / AK)
            load_kv_h(sbase, (it + 2) % ASTAGE, k, v, base, (it + 2) * AK, t);

        uint32_t aK = sbase + s * KVSTB;
        uint32_t aV = sbase + OFFVB + s * KVSTB;

        // ---- S = Q K^T ----
        float sacc[8][4];
        #pragma unroll
        for (int ni = 0; ni < 8; ni++)
            #pragma unroll
            for (int r = 0; r < 4; r++) sacc[ni][r] = 0.f;

        #pragma unroll
        for (int ks = 0; ks < 4; ks++) {
            uint32_t bf[8][2];
            #pragma unroll
            for (int nb = 0; nb < 4; nb++) {
                uint32_t r[4];
                ldmx4(r, aK + (uint32_t)((nb * 16 + kb_row) * KVROWB
                                         + ks * 32 + kb_hi));
                bf[2 * nb][0] = r[0];     bf[2 * nb][1] = r[1];
                bf[2 * nb + 1][0] = r[2]; bf[2 * nb + 1][1] = r[3];
            }
            #pragma unroll
            for (int ni = 0; ni < 8; ni++)
                mma16816(sacc[ni], qf[ks], bf[ni]);
        }

        // ---- online softmax on fragments ----
        float mx1 = -1e30f, mx2 = -1e30f;
        #pragma unroll
        for (int ni = 0; ni < 8; ni++) {
            mx1 = fmaxf(mx1, fmaxf(sacc[ni][0], sacc[ni][1]));
            mx2 = fmaxf(mx2, fmaxf(sacc[ni][2], sacc[ni][3]));
        }
        mx1 = fmaxf(mx1, __shfl_xor_sync(0xffffffffu, mx1, 1));
        mx1 = fmaxf(mx1, __shfl_xor_sync(0xffffffffu, mx1, 2));
        mx2 = fmaxf(mx2, __shfl_xor_sync(0xffffffffu, mx2, 1));
        mx2 = fmaxf(mx2, __shfl_xor_sync(0xffffffffu, mx2, 2));
        float mn1 = fmaxf(m1, mx1), mn2 = fmaxf(m2, mx2);
        float a1 = __expf(m1 - mn1), a2 = __expf(m2 - mn2);
        m1 = mn1; m2 = mn2;

        // P fragments: S C-frag layout == A-frag layout for m16n8k16
        uint32_t ph[8][2];
        float ls1 = 0.f, ls2 = 0.f;
        #pragma unroll
        for (int ni = 0; ni < 8; ni++) {
            float p0 = __expf(sacc[ni][0] - mn1);
            float p1 = __expf(sacc[ni][1] - mn1);
            float p2 = __expf(sacc[ni][2] - mn2);
            float p3 = __expf(sacc[ni][3] - mn2);
            ls1 += p0 + p1; ls2 += p2 + p3;
            ph[ni][0] = packh2(p0, p1);
            ph[ni][1] = packh2(p2, p3);
        }
        ls1 += __shfl_xor_sync(0xffffffffu, ls1, 1);
        ls1 += __shfl_xor_sync(0xffffffffu, ls1, 2);
        ls2 += __shfl_xor_sync(0xffffffffu, ls2, 1);
        ls2 += __shfl_xor_sync(0xffffffffu, ls2, 2);
        l1 = l1 * a1 + ls1;
        l2 = l2 * a2 + ls2;

        #pragma unroll
        for (int ni = 0; ni < 8; ni++) {
            oacc[ni][0] *= a1; oacc[ni][1] *= a1;
            oacc[ni][2] *= a2; oacc[ni][3] *= a2;
        }

        // ---- O += P V ----
        #pragma unroll
        for (int ks = 0; ks < 4; ks++) {
            uint32_t vb[8][2];
            #pragma unroll
            for (int nb = 0; nb < 4; nb++) {
                uint32_t r[4];
                ldmx4t(r, aV + (uint32_t)((16 * ks + vb_row) * KVROWB
                                          + nb * 32 + vb_hi));
                vb[2 * nb][0] = r[0];     vb[2 * nb][1] = r[1];
                vb[2 * nb + 1][0] = r[2]; vb[2 * nb + 1][1] = r[3];
            }
            uint32_t a[4] = {ph[2 * ks][0], ph[2 * ks][1],
                             ph[2 * ks + 1][0], ph[2 * ks + 1][1]};
            #pragma unroll
            for (int ni = 0; ni < 8; ni++)
                mma16816(oacc[ni], a, vb[ni]);
        }
    }

    // ---- normalize + write half ----
    float inv1 = 1.0f / l1, inv2 = 1.0f / l2;
    int r1 = m0 + qrow + gid;
    #pragma unroll
    for (int ni = 0; ni < 8; ni++) {
        int cc = ni * 8 + 2 * qid;
        *(uint32_t*)(o + base + (size_t)r1 * Hdim + cc) =
            packh2(oacc[ni][0] * inv1, oacc[ni][1] * inv1);
        *(uint32_t*)(o + base + (size_t)(r1 + 8) * Hdim + cc) =
            packh2(oacc[ni][2] * inv2, oacc[ni][3] * inv2);
    }
}

// ---------------------------------------------------------------------------
// kernel_launch
// Inputs (metadata order): x, Wq, Wk, Wv, Wo, bo, gamma, beta. Output fp32.
// ---------------------------------------------------------------------------
extern "C" void kernel_launch(void* const* d_in, const int* in_sizes, int n_in,
                              void* d_out, int out_size)
{
    const float* x     = (const float*)d_in[0];
    const float* Wq    = (const float*)d_in[1];
    const float* Wk    = (const float*)d_in[2];
    const float* Wv    = (const float*)d_in[3];
    const float* Wo    = (const float*)d_in[4];
    const float* bo    = (const float*)d_in[5];
    const float* gamma = (const float*)d_in[6];
    const float* beta  = (const float*)d_in[7];
    float* out = (float*)d_out;

    __half *xn, *q, *k, *v, *ao, *wq, *wk, *wv, *wo;
    cudaGetSymbolAddress((void**)&xn, g_xnh);
    cudaGetSymbolAddress((void**)&q,  g_qh);
    cudaGetSymbolAddress((void**)&k,  g_kh);
    cudaGetSymbolAddress((void**)&v,  g_vh);
    cudaGetSymbolAddress((void**)&ao, g_aoh);
    cudaGetSymbolAddress((void**)&wq, g_wqh);
    cudaGetSymbolAddress((void**)&wk, g_wkh);
    cudaGetSymbolAddress((void**)&wv, g_wvh);
    cudaGetSymbolAddress((void**)&wo, g_woh);

    cudaFuncSetAttribute(gemm_qkv, cudaFuncAttributeMaxDynamicSharedMemorySize,
                         GSMEMH);
    cudaFuncSetAttribute(gemm_wo, cudaFuncAttributeMaxDynamicSharedMemorySize,
                         GSMEMH);
    cudaFuncSetAttribute(attn_h, cudaFuncAttributeMaxDynamicSharedMemorySize,
                         ATTN_SMEMH);

    // 0) Convert all four weights to fp16 (one launch, 2048 blocks)
    f2h4_kernel<<<dim3(512, 4), 256>>>(Wq, Wk, Wv, Wo, wq, wk, wv, wo);

    // 1) LayerNorm (fp16 output)
    ln_kernel<<<Mrows, 256>>>(x, gamma, beta, xn);

    // 2) Fused Q/K/V projections (one launch, 768 CTAs)
    gemm_qkv<<<dim3(Hdim / 128, Mrows / 128, 3), 256, GSMEMH>>>(
        xn, wq, wk, wv, q, k, v);

    // 3) Attention (fp16 mma flash, FA2 register pipeline)
    attn_h<<<dim3(Sv / AQ, NHEAD, Bv), 256, ATTN_SMEMH>>>(q, k, v, ao);

    // 4) Output projection + bias + residual (fp32 output)
    gemm_wo<<<dim3(Hdim / 128, Mrows / 128), 256, GSMEMH>>>(ao, wo, out, bo, x);
}